// round 15
// baseline (speedup 1.0000x reference)
#include <cuda_runtime.h>
#include <cuda_fp16.h>
#include <math.h>
#include <stdint.h>

#define N_NODES 20000
#define N_EDGES 640000
#define HDIM    128
#define GDIM    50
#define NLAYERS 6
#define NGRAPH  64
#define CUTOFF  10.0f
#define LOG2F_  0.69314718055994531f
#define PI_     3.14159265358979323846f

#define EPT     128
#define NTILES  (N_EDGES / EPT)
#define EA_STR  72
#define HID_STR 136
#define NODE_TILES ((N_NODES + 127) / 128)
#define SCAN_BLOCKS ((N_NODES + 1023) / 1024)   // 20

// ---------------- device scratch ----------------
static __device__ __align__(16) float  g_h[N_NODES * HDIM];
static __device__ __align__(16) __half g_xf[N_NODES * HDIM];   // fp16 (R15)
static __device__ __align__(16) float  g_agg[N_NODES * HDIM];
static __device__ __align__(16) float  g_d[N_EDGES];
static __device__ __align__(16) float  g_C[N_EDGES];
static __device__ __align__(16) float  g_sums[NGRAPH * HDIM];
static __device__ float g_cnt[NGRAPH];
static __device__ int   g_hist[N_NODES];
static __device__ int   g_bsum[SCAN_BLOCKS];
static __device__ int   g_srcp[N_EDGES];
static __device__ int   g_dstp[N_EDGES];
static __device__ float g_Cp[N_EDGES];
static __device__ float g_dp[N_EDGES];
// prebuilt fp16 B-fragments (m16n8k16 layout)
static __device__ __align__(16) uint2 g_w1f[NLAYERS][2048];
static __device__ __align__(16) uint2 g_w2f[NLAYERS][4096];
static __device__ __align__(16) uint2 g_wAf[NLAYERS][4096];
static __device__ __align__(16) uint2 g_wBf[NLAYERS][4096];
static __device__ __align__(16) uint2 g_wCf[NLAYERS][4096];
static __device__ __align__(16) uint2 g_wO1f[4096];
static __device__ __align__(16) uint2 g_wO2f[4096];

// ---------------- helpers ----------------
__device__ __forceinline__ float sspf_fast(float x) {
    return fmaxf(x, 0.f) + __logf(1.f + __expf(-fabsf(x))) - LOG2F_;
}
__device__ __forceinline__ uint32_t smem_u32(const void* p) {
    uint32_t a;
    asm("{ .reg .u64 t; cvta.to.shared.u64 t, %1; cvt.u32.u64 %0, t; }" : "=r"(a) : "l"(p));
    return a;
}
__device__ __forceinline__ uint32_t f2h2(float lo, float hi) {
    __half2 h = __floats2half2_rn(lo, hi);
    return *reinterpret_cast<uint32_t*>(&h);
}
__device__ __forceinline__ void mma16816(float4& d, const uint32_t a[4], uint2 b) {
    asm volatile(
        "mma.sync.aligned.m16n8k16.row.col.f32.f16.f16.f32 "
        "{%0,%1,%2,%3}, {%4,%5,%6,%7}, {%8,%9}, {%0,%1,%2,%3};\n"
        : "+f"(d.x), "+f"(d.y), "+f"(d.z), "+f"(d.w)
        : "r"(a[0]), "r"(a[1]), "r"(a[2]), "r"(a[3]), "r"(b.x), "r"(b.y));
}
__device__ __forceinline__ void ldsm4(uint32_t r[4], const void* p) {
    uint32_t a = smem_u32(p);
    asm volatile("ldmatrix.sync.aligned.m8n8.x4.shared.b16 {%0,%1,%2,%3}, [%4];"
        : "=r"(r[0]), "=r"(r[1]), "=r"(r[2]), "=r"(r[3]) : "r"(a));
}
#define PAIR_BAR(id) asm volatile("bar.sync %0, 64;" :: "r"(id) : "memory")

// ---------------- precompute ----------------
__global__ void zero_all_kernel() {
    int i = blockIdx.x * blockDim.x + threadIdx.x;
    if (i < N_NODES * HDIM) g_agg[i] = 0.f;
    if (i < N_NODES) g_hist[i] = 0;
    if (i < NGRAPH * HDIM) g_sums[i] = 0.f;
    if (i < NGRAPH) g_cnt[i] = 0.f;
}

__global__ void init_h_kernel(const int* __restrict__ z, const float* __restrict__ emb,
                              const int* __restrict__ batch) {
    int i = blockIdx.x * blockDim.x + threadIdx.x;
    if (i >= N_NODES * HDIM) return;
    int n = i >> 7, j = i & 127;
    g_h[i] = emb[z[n] * HDIM + j];
    if (j == 0) atomicAdd(&g_cnt[batch[n]], 1.0f);
}

__global__ void dist_hist_kernel(const int* __restrict__ src, const int* __restrict__ dst,
                                 const float* __restrict__ pos) {
    int e = blockIdx.x * blockDim.x + threadIdx.x;
    if (e >= N_EDGES) return;
    int s = src[e], t = dst[e];
    float dx = pos[s * 3 + 0] - pos[t * 3 + 0];
    float dy = pos[s * 3 + 1] - pos[t * 3 + 1];
    float dz = pos[s * 3 + 2] - pos[t * 3 + 2];
    float d = sqrtf(dx * dx + dy * dy + dz * dz);
    g_d[e] = d;
    g_C[e] = 0.5f * (cosf(d * (PI_ / CUTOFF)) + 1.0f);
    atomicAdd(&g_hist[t], 1);
}

__global__ void scan1_kernel() {
    __shared__ int s[1024];
    int t = threadIdx.x;
    int idx = blockIdx.x * 1024 + t;
    int v = (idx < N_NODES) ? g_hist[idx] : 0;
    s[t] = v;
    __syncthreads();
    for (int off = 512; off > 0; off >>= 1) {
        if (t < off) s[t] += s[t + off];
        __syncthreads();
    }
    if (t == 0) g_bsum[blockIdx.x] = s[0];
}
__global__ void scan2_kernel() {
    if (threadIdx.x == 0) {
        int run = 0;
        for (int b = 0; b < SCAN_BLOCKS; b++) {
            int c = g_bsum[b];
            g_bsum[b] = run;
            run += c;
        }
    }
}
__global__ void scan3_kernel() {
    __shared__ int s[1024];
    int t = threadIdx.x;
    int idx = blockIdx.x * 1024 + t;
    int v = (idx < N_NODES) ? g_hist[idx] : 0;
    s[t] = v;
    __syncthreads();
    for (int off = 1; off < 1024; off <<= 1) {
        int u = (t >= off) ? s[t - off] : 0;
        __syncthreads();
        s[t] += u;
        __syncthreads();
    }
    if (idx < N_NODES) g_hist[idx] = s[t] - v + g_bsum[blockIdx.x];
}

__global__ void scatter_kernel(const int* __restrict__ src, const int* __restrict__ dst) {
    int e = blockIdx.x * blockDim.x + threadIdx.x;
    if (e >= N_EDGES) return;
    int d = dst[e];
    int p = atomicAdd(&g_hist[d], 1);
    g_srcp[p] = src[e];
    g_dstp[p] = d;
    g_Cp[p]   = g_C[e];
    g_dp[p]   = g_d[e];
}

__device__ __forceinline__ uint2 frag_of(const float* w, int k0, int n) {
    return make_uint2(f2h2(w[k0 * 128 + n], w[(k0 + 1) * 128 + n]),
                      f2h2(w[(k0 + 8) * 128 + n], w[(k0 + 9) * 128 + n]));
}
__global__ void build_frags_kernel(const float* __restrict__ mlp_w1,
                                   const float* __restrict__ mlp_w2,
                                   const float* __restrict__ conv_w2,
                                   const float* __restrict__ lin_w,
                                   const float* __restrict__ conv_w1,
                                   const float* __restrict__ out1_w,
                                   const float* __restrict__ out2_w) {
    int i = blockIdx.x * blockDim.x + threadIdx.x;
    if (i >= NLAYERS * 4096) return;
    int l = i / 4096, j = i % 4096;
    int lane = j & 31;
    int g_ = lane >> 2, t_ = lane & 3;
    {
        int kt = (j >> 5) & 7, nt = j >> 8;
        int k0 = kt * 16 + 2 * t_, n = nt * 8 + g_;
        g_w2f[l][j] = frag_of(mlp_w2 + (size_t)l * 16384, k0, n);
        g_wAf[l][j] = frag_of(conv_w2 + (size_t)l * 16384, k0, n);
        g_wBf[l][j] = frag_of(lin_w + (size_t)l * 16384, k0, n);
        g_wCf[l][j] = frag_of(conv_w1 + (size_t)l * 16384, k0, n);
        if (l == 0) {
            g_wO1f[j] = frag_of(out1_w, k0, n);
            g_wO2f[j] = frag_of(out2_w, k0, n);
        }
    }
    if (j < 2048) {
        int kt = (j >> 5) & 3, nt = j >> 7;
        int k0 = kt * 16 + 2 * t_, n = nt * 8 + g_;
        const float* w1 = mlp_w1 + (size_t)l * GDIM * 128;
        float v0 = (k0     < GDIM) ? w1[k0 * 128 + n]       : 0.f;
        float v1 = (k0 + 1 < GDIM) ? w1[(k0 + 1) * 128 + n] : 0.f;
        float v2 = (k0 + 8 < GDIM) ? w1[(k0 + 8) * 128 + n] : 0.f;
        float v3 = (k0 + 9 < GDIM) ? w1[(k0 + 9) * 128 + n] : 0.f;
        g_w1f[l][j] = make_uint2(f2h2(v0, v1), f2h2(v2, v3));
    }
}

// ---------------- initial xf = h @ conv_w1[0]  (fp16 MMA, fp16 out) --------
__global__ __launch_bounds__(256, 2) void xf0_kernel() {
    extern __shared__ char smraw[];
    __half* in_s = (__half*)smraw;             // 34816
    uint2*  wf   = (uint2*)(smraw + 34816);    // 32768
    int tid = threadIdx.x;
    int wid = tid >> 5;
    int lid = tid & 31;
    int gid = lid >> 2;
    int tg  = lid & 3;
    int lrow = lid & 15;
    int lcol = (lid >> 4) << 3;

    for (int i = tid; i < 2048; i += 256)
        ((uint4*)wf)[i] = ((const uint4*)g_wCf[0])[i];

    int n0 = blockIdx.x * 128;
    for (int i = tid; i < 128 * 32; i += 256) {
        int r = i >> 5, c4 = i & 31;
        float4 v = make_float4(0.f, 0.f, 0.f, 0.f);
        if (n0 + r < N_NODES)
            v = ((const float4*)&g_h[(size_t)(n0 + r) * 128])[c4];
        *(uint2*)&in_s[r * HID_STR + c4 * 4] = make_uint2(f2h2(v.x, v.y), f2h2(v.z, v.w));
    }
    __syncthreads();

    int mbase = (wid & 3) * 32;
    int nb    = (wid >> 2) * 8;
    float4 acc[2][8];
    #pragma unroll
    for (int mi = 0; mi < 2; mi++)
        #pragma unroll
        for (int ni = 0; ni < 8; ni++)
            acc[mi][ni] = make_float4(0.f, 0.f, 0.f, 0.f);
    #pragma unroll
    for (int kt = 0; kt < 8; kt++) {
        uint32_t a0[4], a1[4];
        ldsm4(a0, &in_s[(mbase + lrow) * HID_STR + kt * 16 + lcol]);
        ldsm4(a1, &in_s[(mbase + 16 + lrow) * HID_STR + kt * 16 + lcol]);
        #pragma unroll
        for (int ni = 0; ni < 8; ni++) {
            uint2 b = wf[((nb + ni) * 8 + kt) * 32 + lid];
            mma16816(acc[0][ni], a0, b);
            mma16816(acc[1][ni], a1, b);
        }
    }
    #pragma unroll
    for (int mi = 0; mi < 2; mi++) {
        int ra = mbase + mi * 16 + gid;
        int rb = ra + 8;
        int na = n0 + ra, nbn = n0 + rb;
        #pragma unroll
        for (int ni = 0; ni < 8; ni++) {
            int c0 = (nb + ni) * 8 + 2 * tg;
            float4 v = acc[mi][ni];
            if (na < N_NODES)
                *(uint32_t*)&g_xf[(size_t)na * 128 + c0] = f2h2(v.x, v.y);
            if (nbn < N_NODES)
                *(uint32_t*)&g_xf[(size_t)nbn * 128 + c0] = f2h2(v.z, v.w);
        }
    }
}

// ---------------- fp16 MMA edge kernel ----------------
__global__ __launch_bounds__(256, 2) void edge_mma_kernel(
        int layer, const float* __restrict__ b1, const float* __restrict__ b2) {
    extern __shared__ char smraw[];
    __half* ea_s  = (__half*)smraw;                   // 18432
    __half* hid_s = (__half*)(smraw + 18432);         // 34816
    __half* msg_h = hid_s;                            // aliases hid (post-GEMM2)
    uint2*  w1f   = (uint2*)(smraw + 53248);          // 16384
    uint2*  w2f   = (uint2*)(smraw + 69632);          // 32768
    float*  b1_s  = (float*)(smraw + 102400);
    float*  b2_s  = b1_s + 128;
    float*  C_s   = b2_s + 128;
    int*    src_s = (int*)(C_s + 128);
    int*    dst_s = src_s + 128;

    int tid = threadIdx.x;
    int wid = tid >> 5;
    int lid = tid & 31;
    int gid = lid >> 2;
    int tg  = lid & 3;
    int lrow = lid & 15;
    int lcol = (lid >> 4) << 3;
    int strip = wid & 3;
    int half  = wid >> 2;
    int bar_id = 1 + strip;

    const float step  = CUTOFF / (GDIM - 1);
    const float inv_step = (GDIM - 1) / CUTOFF;
    const float coeff = -0.5f / (step * step);

    if (tid < 128) { b1_s[tid] = b1[tid]; b2_s[tid] = b2[tid]; }
    for (int i = tid; i < 1024; i += 256)
        ((uint4*)w1f)[i] = ((const uint4*)g_w1f[layer])[i];
    for (int i = tid; i < 2048; i += 256)
        ((uint4*)w2f)[i] = ((const uint4*)g_w2f[layer])[i];
    __syncthreads();

    int mbase = strip * 32;
    int nb    = half * 8;
    int rchunk = 2 * strip + half;
    int rr0 = rchunk * 16;

    int psrc = 0, pdst = 0;
    float pC = 0.f, pd = 0.f;
    int t = blockIdx.x;
    if (t < NTILES && tid < 128) {
        int e0 = t * EPT;
        psrc = g_srcp[e0 + tid];
        pdst = g_dstp[e0 + tid];
        pC   = g_Cp[e0 + tid];
        pd   = g_dp[e0 + tid];
    }

    for (; t < NTILES; t += gridDim.x) {
        // commit scalars + compute gaussian rows in-kernel (±6 window)
        if (tid < 128) {
            src_s[tid] = psrc; dst_s[tid] = pdst; C_s[tid] = pC;
            uint4 z4 = make_uint4(0, 0, 0, 0);
            #pragma unroll
            for (int j = 0; j < 8; j++)
                *(uint4*)&ea_s[tid * EA_STR + j * 8] = z4;
            int c0 = (int)rintf(pd * inv_step);
            #pragma unroll
            for (int k = -6; k <= 6; k++) {
                int c = c0 + k;
                if (c >= 0 && c < GDIM) {
                    float diff = pd - c * step;
                    ea_s[tid * EA_STR + c] = __float2half_rn(__expf(coeff * diff * diff));
                }
            }
        }
        __syncthreads();   // S1

        float4 acc[2][8];
        #pragma unroll
        for (int mi = 0; mi < 2; mi++)
            #pragma unroll
            for (int ni = 0; ni < 8; ni++)
                acc[mi][ni] = make_float4(0.f, 0.f, 0.f, 0.f);

        // GEMM1: K=64
        #pragma unroll
        for (int kt = 0; kt < 4; kt++) {
            uint32_t a0[4], a1[4];
            ldsm4(a0, &ea_s[(mbase + lrow) * EA_STR + kt * 16 + lcol]);
            ldsm4(a1, &ea_s[(mbase + 16 + lrow) * EA_STR + kt * 16 + lcol]);
            #pragma unroll
            for (int ni = 0; ni < 8; ni++) {
                uint2 b = w1f[((nb + ni) * 4 + kt) * 32 + lid];
                mma16816(acc[0][ni], a0, b);
                mma16816(acc[1][ni], a1, b);
            }
        }

        // ssp -> fp16 HID
        #pragma unroll
        for (int mi = 0; mi < 2; mi++) {
            int ra = mbase + mi * 16 + gid;
            int rb = ra + 8;
            #pragma unroll
            for (int ni = 0; ni < 8; ni++) {
                int c0 = (nb + ni) * 8 + 2 * tg;
                float4 v = acc[mi][ni];
                float ba = b1_s[c0], bb = b1_s[c0 + 1];
                *(uint32_t*)&hid_s[ra * HID_STR + c0] =
                    f2h2(sspf_fast(v.x + ba), sspf_fast(v.y + bb));
                *(uint32_t*)&hid_s[rb * HID_STR + c0] =
                    f2h2(sspf_fast(v.z + ba), sspf_fast(v.w + bb));
            }
        }
        PAIR_BAR(bar_id);   // P1

        int tn = t + gridDim.x;
        if (tn < NTILES && tid < 128) {
            int e0n = tn * EPT;
            psrc = g_srcp[e0n + tid];
            pdst = g_dstp[e0n + tid];
            pC   = g_Cp[e0n + tid];
            pd   = g_dp[e0n + tid];
        }

        #pragma unroll
        for (int mi = 0; mi < 2; mi++)
            #pragma unroll
            for (int ni = 0; ni < 8; ni++)
                acc[mi][ni] = make_float4(0.f, 0.f, 0.f, 0.f);

        // GEMM2: K=128
        #pragma unroll
        for (int kt = 0; kt < 8; kt++) {
            uint32_t a0[4], a1[4];
            ldsm4(a0, &hid_s[(mbase + lrow) * HID_STR + kt * 16 + lcol]);
            ldsm4(a1, &hid_s[(mbase + 16 + lrow) * HID_STR + kt * 16 + lcol]);
            #pragma unroll
            for (int ni = 0; ni < 8; ni++) {
                uint2 b = w2f[((nb + ni) * 8 + kt) * 32 + lid];
                mma16816(acc[0][ni], a0, b);
                mma16816(acc[1][ni], a1, b);
            }
        }
        PAIR_BAR(bar_id);   // P2

        // stage fp16 msg = (C2+b2)*C
        #pragma unroll
        for (int mi = 0; mi < 2; mi++) {
            int ra = mbase + mi * 16 + gid;
            int rb = ra + 8;
            float Ca = C_s[ra], Cb = C_s[rb];
            #pragma unroll
            for (int ni = 0; ni < 8; ni++) {
                int c0 = (nb + ni) * 8 + 2 * tg;
                float4 v = acc[mi][ni];
                float2 bv = *(const float2*)&b2_s[c0];
                *(uint32_t*)&msg_h[ra * HID_STR + c0] =
                    f2h2((v.x + bv.x) * Ca, (v.y + bv.y) * Ca);
                *(uint32_t*)&msg_h[rb * HID_STR + c0] =
                    f2h2((v.z + bv.x) * Cb, (v.w + bv.y) * Cb);
            }
        }
        PAIR_BAR(bar_id);   // P3

        // segmented reduce (fp16 msg × fp16 xf gather, fp32 accumulate)
        {
            int cg = lid;
            float4 run = make_float4(0.f, 0.f, 0.f, 0.f);
            int cur = dst_s[rr0];
            #pragma unroll
            for (int j = 0; j < 16; j++) {
                int dd = dst_s[rr0 + j];
                uint2 mh = *(uint2*)&msg_h[(rr0 + j) * HID_STR + cg * 4];
                float2 m01 = __half22float2(*(__half2*)&mh.x);
                float2 m23 = __half22float2(*(__half2*)&mh.y);
                uint2 xh = *(const uint2*)&g_xf[(size_t)src_s[rr0 + j] * 128 + cg * 4];
                float2 x01 = __half22float2(*(__half2*)&xh.x);
                float2 x23 = __half22float2(*(__half2*)&xh.y);
                if (dd != cur) {
                    atomicAdd((float4*)&g_agg[(size_t)cur * 128 + cg * 4], run);
                    run = make_float4(0.f, 0.f, 0.f, 0.f);
                    cur = dd;
                }
                run.x += m01.x * x01.x; run.y += m01.y * x01.y;
                run.z += m23.x * x23.x; run.w += m23.y * x23.y;
            }
            atomicAdd((float4*)&g_agg[(size_t)cur * 128 + cg * 4], run);
        }
        __syncthreads();   // S2
    }
}

// ---------------- fused node kernel ----------------
__global__ __launch_bounds__(256, 1) void node_fused_kernel(
        int layer, const float* __restrict__ bA, const float* __restrict__ bB,
        const float* __restrict__ bO1, const float* __restrict__ bO2,
        const int* __restrict__ batch, int do_c) {
    extern __shared__ char smraw[];
    __half* in_s = (__half*)smraw;                     // 34816
    __half* x_s  = (__half*)(smraw + 34816);           // 34816
    uint2*  wAf  = (uint2*)(smraw + 69632);
    uint2*  wBf  = (uint2*)(smraw + 102400);
    uint2*  wCf  = (uint2*)(smraw + 135168);
    uint2*  wDf  = (uint2*)(smraw + 167936);
    float*  bA_s = (float*)(smraw + 200704);
    float*  bB_s = bA_s + 128;
    float*  bO1_s = bB_s + 128;
    float*  bO2_s = bO1_s + 128;
    int*    batch_s = (int*)(bO2_s + 128);

    int tid = threadIdx.x;
    int wid = tid >> 5;
    int lid = tid & 31;
    int gid = lid >> 2;
    int tg  = lid & 3;
    int lrow = lid & 15;
    int lcol = (lid >> 4) << 3;
    int do_out = !do_c;

    if (tid < 128) {
        bA_s[tid] = bA[tid]; bB_s[tid] = bB[tid];
        if (do_out) { bO1_s[tid] = bO1[tid]; bO2_s[tid] = bO2[tid]; }
    }
    for (int i = tid; i < 2048; i += 256) {
        ((uint4*)wAf)[i] = ((const uint4*)g_wAf[layer])[i];
        ((uint4*)wBf)[i] = ((const uint4*)g_wBf[layer])[i];
        if (do_c) {
            ((uint4*)wCf)[i] = ((const uint4*)g_wCf[layer + 1])[i];
        } else {
            ((uint4*)wCf)[i] = ((const uint4*)g_wO1f)[i];
            ((uint4*)wDf)[i] = ((const uint4*)g_wO2f)[i];
        }
    }
    __syncthreads();

    int mbase = (wid & 3) * 32;
    int nb    = (wid >> 2) * 8;

    for (int tile = blockIdx.x; tile < NODE_TILES; tile += gridDim.x) {
        int n0 = tile * 128;
        for (int i = tid; i < 128 * 32; i += 256) {
            int r = i >> 5, c4 = i & 31;
            float4 v = make_float4(0.f, 0.f, 0.f, 0.f);
            if (n0 + r < N_NODES) {
                v = ((const float4*)&g_agg[(size_t)(n0 + r) * 128])[c4];
                ((float4*)&g_agg[(size_t)(n0 + r) * 128])[c4] =
                    make_float4(0.f, 0.f, 0.f, 0.f);
            }
            *(uint2*)&in_s[r * HID_STR + c4 * 4] = make_uint2(f2h2(v.x, v.y), f2h2(v.z, v.w));
        }
        if (do_out && tid < 128)
            batch_s[tid] = (n0 + tid < N_NODES) ? batch[n0 + tid] : 0;
        __syncthreads();

        float4 acc[2][8];
        // ---- GEMM A: x = ssp(agg @ wA + bA) ----
        #pragma unroll
        for (int mi = 0; mi < 2; mi++)
            #pragma unroll
            for (int ni = 0; ni < 8; ni++)
                acc[mi][ni] = make_float4(0.f, 0.f, 0.f, 0.f);
        #pragma unroll
        for (int kt = 0; kt < 8; kt++) {
            uint32_t a0[4], a1[4];
            ldsm4(a0, &in_s[(mbase + lrow) * HID_STR + kt * 16 + lcol]);
            ldsm4(a1, &in_s[(mbase + 16 + lrow) * HID_STR + kt * 16 + lcol]);
            #pragma unroll
            for (int ni = 0; ni < 8; ni++) {
                uint2 b = wAf[((nb + ni) * 8 + kt) * 32 + lid];
                mma16816(acc[0][ni], a0, b);
                mma16816(acc[1][ni], a1, b);
            }
        }
        #pragma unroll
        for (int mi = 0; mi < 2; mi++) {
            int ra = mbase + mi * 16 + gid;
            int rb = ra + 8;
            #pragma unroll
            for (int ni = 0; ni < 8; ni++) {
                int c0 = (nb + ni) * 8 + 2 * tg;
                float4 v = acc[mi][ni];
                float ba = bA_s[c0], bb = bA_s[c0 + 1];
                *(uint32_t*)&x_s[ra * HID_STR + c0] =
                    f2h2(sspf_fast(v.x + ba), sspf_fast(v.y + bb));
                *(uint32_t*)&x_s[rb * HID_STR + c0] =
                    f2h2(sspf_fast(v.z + ba), sspf_fast(v.w + bb));
            }
        }
        __syncthreads();

        // ---- GEMM B: h += x @ wB + bB ----
        #pragma unroll
        for (int mi = 0; mi < 2; mi++)
            #pragma unroll
            for (int ni = 0; ni < 8; ni++)
                acc[mi][ni] = make_float4(0.f, 0.f, 0.f, 0.f);
        #pragma unroll
        for (int kt = 0; kt < 8; kt++) {
            uint32_t a0[4], a1[4];
            ldsm4(a0, &x_s[(mbase + lrow) * HID_STR + kt * 16 + lcol]);
            ldsm4(a1, &x_s[(mbase + 16 + lrow) * HID_STR + kt * 16 + lcol]);
            #pragma unroll
            for (int ni = 0; ni < 8; ni++) {
                uint2 b = wBf[((nb + ni) * 8 + kt) * 32 + lid];
                mma16816(acc[0][ni], a0, b);
                mma16816(acc[1][ni], a1, b);
            }
        }
        #pragma unroll
        for (int mi = 0; mi < 2; mi++) {
            int ra = mbase + mi * 16 + gid;
            int rb = ra + 8;
            int na = n0 + ra, nbn = n0 + rb;
            #pragma unroll
            for (int ni = 0; ni < 8; ni++) {
                int c0 = (nb + ni) * 8 + 2 * tg;
                float4 v = acc[mi][ni];
                float ba = bB_s[c0], bb = bB_s[c0 + 1];
                float hx = 0.f, hy = 0.f, hz = 0.f, hw = 0.f;
                if (na < N_NODES) {
                    float2 hv = *(float2*)&g_h[(size_t)na * 128 + c0];
                    hx = hv.x + v.x + ba;
                    hy = hv.y + v.y + bb;
                    *(float2*)&g_h[(size_t)na * 128 + c0] = make_float2(hx, hy);
                }
                if (nbn < N_NODES) {
                    float2 hv = *(float2*)&g_h[(size_t)nbn * 128 + c0];
                    hz = hv.x + v.z + ba;
                    hw = hv.y + v.w + bb;
                    *(float2*)&g_h[(size_t)nbn * 128 + c0] = make_float2(hz, hw);
                }
                *(uint32_t*)&in_s[ra * HID_STR + c0] = f2h2(hx, hy);
                *(uint32_t*)&in_s[rb * HID_STR + c0] = f2h2(hz, hw);
            }
        }
        __syncthreads();

        if (do_c) {
            // ---- GEMM C: xf = h @ wC  (fp16 out) ----
            #pragma unroll
            for (int mi = 0; mi < 2; mi++)
                #pragma unroll
                for (int ni = 0; ni < 8; ni++)
                    acc[mi][ni] = make_float4(0.f, 0.f, 0.f, 0.f);
            #pragma unroll
            for (int kt = 0; kt < 8; kt++) {
                uint32_t a0[4], a1[4];
                ldsm4(a0, &in_s[(mbase + lrow) * HID_STR + kt * 16 + lcol]);
                ldsm4(a1, &in_s[(mbase + 16 + lrow) * HID_STR + kt * 16 + lcol]);
                #pragma unroll
                for (int ni = 0; ni < 8; ni++) {
                    uint2 b = wCf[((nb + ni) * 8 + kt) * 32 + lid];
                    mma16816(acc[0][ni], a0, b);
                    mma16816(acc[1][ni], a1, b);
                }
            }
            #pragma unroll
            for (int mi = 0; mi < 2; mi++) {
                int ra = mbase + mi * 16 + gid;
                int rb = ra + 8;
                int na = n0 + ra, nbn = n0 + rb;
                #pragma unroll
                for (int ni = 0; ni < 8; ni++) {
                    int c0 = (nb + ni) * 8 + 2 * tg;
                    float4 v = acc[mi][ni];
                    if (na < N_NODES)
                        *(uint32_t*)&g_xf[(size_t)na * 128 + c0] = f2h2(v.x, v.y);
                    if (nbn < N_NODES)
                        *(uint32_t*)&g_xf[(size_t)nbn * 128 + c0] = f2h2(v.z, v.w);
                }
            }
        } else {
            // ---- output head: x = ssp(h @ out1 + bO1) ----
            #pragma unroll
            for (int mi = 0; mi < 2; mi++)
                #pragma unroll
                for (int ni = 0; ni < 8; ni++)
                    acc[mi][ni] = make_float4(0.f, 0.f, 0.f, 0.f);
            #pragma unroll
            for (int kt = 0; kt < 8; kt++) {
                uint32_t a0[4], a1[4];
                ldsm4(a0, &in_s[(mbase + lrow) * HID_STR + kt * 16 + lcol]);
                ldsm4(a1, &in_s[(mbase + 16 + lrow) * HID_STR + kt * 16 + lcol]);
                #pragma unroll
                for (int ni = 0; ni < 8; ni++) {
                    uint2 b = wCf[((nb + ni) * 8 + kt) * 32 + lid];
                    mma16816(acc[0][ni], a0, b);
                    mma16816(acc[1][ni], a1, b);
                }
            }
            #pragma unroll
            for (int mi = 0; mi < 2; mi++) {
                int ra = mbase + mi * 16 + gid;
                int rb = ra + 8;
                #pragma unroll
                for (int ni = 0; ni < 8; ni++) {
                    int c0 = (nb + ni) * 8 + 2 * tg;
                    float4 v = acc[mi][ni];
                    float ba = bO1_s[c0], bb = bO1_s[c0 + 1];
                    *(uint32_t*)&x_s[ra * HID_STR + c0] =
                        f2h2(sspf_fast(v.x + ba), sspf_fast(v.y + bb));
                    *(uint32_t*)&x_s[rb * HID_STR + c0] =
                        f2h2(sspf_fast(v.z + ba), sspf_fast(v.w + bb));
                }
            }
            __syncthreads();

            // ---- output head: out = x @ out2 + bO2 -> g_sums[batch] ----
            #pragma unroll
            for (int mi = 0; mi < 2; mi++)
                #pragma unroll
                for (int ni = 0; ni < 8; ni++)
                    acc[mi][ni] = make_float4(0.f, 0.f, 0.f, 0.f);
            #pragma unroll
            for (int kt = 0; kt < 8; kt++) {
                uint32_t a0[4], a1[4];
                ldsm4(a0, &x_s[(mbase + lrow) * HID_STR + kt * 16 + lcol]);
                ldsm4(a1, &x_s[(mbase + 16 + lrow) * HID_STR + kt * 16 + lcol]);
                #pragma unroll
                for (int ni = 0; ni < 8; ni++) {
                    uint2 b = wDf[((nb + ni) * 8 + kt) * 32 + lid];
                    mma16816(acc[0][ni], a0, b);
                    mma16816(acc[1][ni], a1, b);
                }
            }
            #pragma unroll
            for (int mi = 0; mi < 2; mi++) {
                int ra = mbase + mi * 16 + gid;
                int rb = ra + 8;
                int na = n0 + ra, nbn = n0 + rb;
                #pragma unroll
                for (int ni = 0; ni < 8; ni++) {
                    int c0 = (nb + ni) * 8 + 2 * tg;
                    float4 v = acc[mi][ni];
                    float2 bv = *(const float2*)&bO2_s[c0];
                    if (na < N_NODES) {
                        float2 o = make_float2(v.x + bv.x, v.y + bv.y);
                        atomicAdd((float2*)&g_sums[batch_s[ra] * 128 + c0], o);
                    }
                    if (nbn < N_NODES) {
                        float2 o = make_float2(v.z + bv.x, v.w + bv.y);
                        atomicAdd((float2*)&g_sums[batch_s[rb] * 128 + c0], o);
                    }
                }
            }
        }
        __syncthreads();
    }
}

__global__ void finalize_kernel(float* __restrict__ out) {
    int i = blockIdx.x * blockDim.x + threadIdx.x;
    if (i >= NGRAPH * HDIM) return;
    out[i] = g_sums[i] / fmaxf(g_cnt[i >> 7], 1.0f);
}

// ---------------- launcher ----------------
extern "C" void kernel_launch(void* const* d_in, const int* in_sizes, int n_in,
                              void* d_out, int out_size) {
    const int*   z       = (const int*)d_in[0];
    const float* pos     = (const float*)d_in[1];
    const int*   ei      = (const int*)d_in[2];
    const int*   batch   = (const int*)d_in[3];
    const float* emb     = (const float*)d_in[4];
    const float* mlp_w1  = (const float*)d_in[5];
    const float* mlp_b1  = (const float*)d_in[6];
    const float* mlp_w2  = (const float*)d_in[7];
    const float* mlp_b2  = (const float*)d_in[8];
    const float* conv_w1 = (const float*)d_in[9];
    const float* conv_w2 = (const float*)d_in[10];
    const float* conv_b2 = (const float*)d_in[11];
    const float* lin_w   = (const float*)d_in[12];
    const float* lin_b   = (const float*)d_in[13];
    const float* out1_w  = (const float*)d_in[14];
    const float* out1_b  = (const float*)d_in[15];
    const float* out2_w  = (const float*)d_in[16];
    const float* out2_b  = (const float*)d_in[17];
    float* out = (float*)d_out;

    const int* src = ei;
    const int* dst = ei + N_EDGES;

    const int EDGE_SMEM = 104960;
    const int NODE_SMEM = 203264;
    const int XF0_SMEM  = 67584;

    cudaFuncSetAttribute(edge_mma_kernel, cudaFuncAttributeMaxDynamicSharedMemorySize, EDGE_SMEM);
    cudaFuncSetAttribute(node_fused_kernel, cudaFuncAttributeMaxDynamicSharedMemorySize, NODE_SMEM);
    cudaFuncSetAttribute(xf0_kernel, cudaFuncAttributeMaxDynamicSharedMemorySize, XF0_SMEM);

    zero_all_kernel<<<(N_NODES * HDIM + 255) / 256, 256>>>();
    init_h_kernel<<<(N_NODES * HDIM + 255) / 256, 256>>>(z, emb, batch);
    dist_hist_kernel<<<(N_EDGES + 255) / 256, 256>>>(src, dst, pos);
    scan1_kernel<<<SCAN_BLOCKS, 1024>>>();
    scan2_kernel<<<1, 32>>>();
    scan3_kernel<<<SCAN_BLOCKS, 1024>>>();
    scatter_kernel<<<(N_EDGES + 255) / 256, 256>>>(src, dst);
    build_frags_kernel<<<(NLAYERS * 4096 + 255) / 256, 256>>>(
        mlp_w1, mlp_w2, conv_w2, lin_w, conv_w1, out1_w, out2_w);

    xf0_kernel<<<NODE_TILES, 256, XF0_SMEM>>>();   // xf for layer 0

    for (int l = 0; l < NLAYERS; l++) {
        edge_mma_kernel<<<296, 256, EDGE_SMEM>>>(
            l, mlp_b1 + (size_t)l * 128, mlp_b2 + (size_t)l * 128);
        int do_c = (l < NLAYERS - 1) ? 1 : 0;
        node_fused_kernel<<<148, 256, NODE_SMEM>>>(
            l, conv_b2 + (size_t)l * 128, lin_b + (size_t)l * 128,
            out1_b, out2_b, batch, do_c);
    }

    finalize_kernel<<<(NGRAPH * HDIM + 255) / 256, 256>>>(out);
}

// round 16
// speedup vs baseline: 1.0793x; 1.0793x over previous
#include <cuda_runtime.h>
#include <cuda_fp16.h>
#include <math.h>
#include <stdint.h>

#define N_NODES 20000
#define N_EDGES 640000
#define HDIM    128
#define GDIM    50
#define NLAYERS 6
#define NGRAPH  64
#define CUTOFF  10.0f
#define LOG2F_  0.69314718055994531f
#define PI_     3.14159265358979323846f

#define EPT     128
#define NTILES  (N_EDGES / EPT)
#define EA_STR  72
#define HID_STR 136
#define NODE_TILES ((N_NODES + 127) / 128)
#define SCAN_BLOCKS ((N_NODES + 1023) / 1024)   // 20

// ---------------- device scratch ----------------
static __device__ __align__(16) float  g_h[N_NODES * HDIM];
static __device__ __align__(16) float  g_xf[N_NODES * HDIM];
static __device__ __align__(16) float  g_agg[N_NODES * HDIM];
static __device__ __align__(16) float  g_d[N_EDGES];
static __device__ __align__(16) float  g_C[N_EDGES];
static __device__ __align__(16) float  g_sums[NGRAPH * HDIM];
static __device__ float g_cnt[NGRAPH];
static __device__ int   g_hist[N_NODES];
static __device__ int   g_bsum[SCAN_BLOCKS];
static __device__ int   g_srcp[N_EDGES];
static __device__ int   g_dstp[N_EDGES];
static __device__ float g_Cp[N_EDGES];
static __device__ float g_dp[N_EDGES];
// prebuilt fp16 B-fragments (m16n8k16 layout)
static __device__ __align__(16) uint2 g_w1f[NLAYERS][2048];
static __device__ __align__(16) uint2 g_w2f[NLAYERS][4096];
static __device__ __align__(16) uint2 g_wAf[NLAYERS][4096];
static __device__ __align__(16) uint2 g_wBf[NLAYERS][4096];
static __device__ __align__(16) uint2 g_wCf[NLAYERS][4096];
static __device__ __align__(16) uint2 g_wO1f[4096];
static __device__ __align__(16) uint2 g_wO2f[4096];

// ---------------- helpers ----------------
__device__ __forceinline__ float sspf_fast(float x) {
    return fmaxf(x, 0.f) + __logf(1.f + __expf(-fabsf(x))) - LOG2F_;
}
__device__ __forceinline__ uint32_t smem_u32(const void* p) {
    uint32_t a;
    asm("{ .reg .u64 t; cvta.to.shared.u64 t, %1; cvt.u32.u64 %0, t; }" : "=r"(a) : "l"(p));
    return a;
}
__device__ __forceinline__ uint32_t f2h2(float lo, float hi) {
    __half2 h = __floats2half2_rn(lo, hi);
    return *reinterpret_cast<uint32_t*>(&h);
}
__device__ __forceinline__ void mma16816(float4& d, const uint32_t a[4], uint2 b) {
    asm volatile(
        "mma.sync.aligned.m16n8k16.row.col.f32.f16.f16.f32 "
        "{%0,%1,%2,%3}, {%4,%5,%6,%7}, {%8,%9}, {%0,%1,%2,%3};\n"
        : "+f"(d.x), "+f"(d.y), "+f"(d.z), "+f"(d.w)
        : "r"(a[0]), "r"(a[1]), "r"(a[2]), "r"(a[3]), "r"(b.x), "r"(b.y));
}
__device__ __forceinline__ void ldsm4(uint32_t r[4], const void* p) {
    uint32_t a = smem_u32(p);
    asm volatile("ldmatrix.sync.aligned.m8n8.x4.shared.b16 {%0,%1,%2,%3}, [%4];"
        : "=r"(r[0]), "=r"(r[1]), "=r"(r[2]), "=r"(r[3]) : "r"(a));
}
#define PAIR_BAR(id) asm volatile("bar.sync %0, 64;" :: "r"(id) : "memory")

// ---------------- precompute ----------------
__global__ void zero_all_kernel() {
    int i = blockIdx.x * blockDim.x + threadIdx.x;
    if (i < N_NODES * HDIM) g_agg[i] = 0.f;
    if (i < N_NODES) g_hist[i] = 0;
    if (i < NGRAPH * HDIM) g_sums[i] = 0.f;
    if (i < NGRAPH) g_cnt[i] = 0.f;
}

__global__ void init_h_kernel(const int* __restrict__ z, const float* __restrict__ emb,
                              const int* __restrict__ batch) {
    int i = blockIdx.x * blockDim.x + threadIdx.x;
    if (i >= N_NODES * HDIM) return;
    int n = i >> 7, j = i & 127;
    g_h[i] = emb[z[n] * HDIM + j];
    if (j == 0) atomicAdd(&g_cnt[batch[n]], 1.0f);
}

__global__ void dist_hist_kernel(const int* __restrict__ src, const int* __restrict__ dst,
                                 const float* __restrict__ pos) {
    int e = blockIdx.x * blockDim.x + threadIdx.x;
    if (e >= N_EDGES) return;
    int s = src[e], t = dst[e];
    float dx = pos[s * 3 + 0] - pos[t * 3 + 0];
    float dy = pos[s * 3 + 1] - pos[t * 3 + 1];
    float dz = pos[s * 3 + 2] - pos[t * 3 + 2];
    float d = sqrtf(dx * dx + dy * dy + dz * dz);
    g_d[e] = d;
    g_C[e] = 0.5f * (cosf(d * (PI_ / CUTOFF)) + 1.0f);
    atomicAdd(&g_hist[t], 1);
}

__global__ void scan1_kernel() {
    __shared__ int s[1024];
    int t = threadIdx.x;
    int idx = blockIdx.x * 1024 + t;
    int v = (idx < N_NODES) ? g_hist[idx] : 0;
    s[t] = v;
    __syncthreads();
    for (int off = 512; off > 0; off >>= 1) {
        if (t < off) s[t] += s[t + off];
        __syncthreads();
    }
    if (t == 0) g_bsum[blockIdx.x] = s[0];
}
__global__ void scan2_kernel() {
    if (threadIdx.x == 0) {
        int run = 0;
        for (int b = 0; b < SCAN_BLOCKS; b++) {
            int c = g_bsum[b];
            g_bsum[b] = run;
            run += c;
        }
    }
}
__global__ void scan3_kernel() {
    __shared__ int s[1024];
    int t = threadIdx.x;
    int idx = blockIdx.x * 1024 + t;
    int v = (idx < N_NODES) ? g_hist[idx] : 0;
    s[t] = v;
    __syncthreads();
    for (int off = 1; off < 1024; off <<= 1) {
        int u = (t >= off) ? s[t - off] : 0;
        __syncthreads();
        s[t] += u;
        __syncthreads();
    }
    if (idx < N_NODES) g_hist[idx] = s[t] - v + g_bsum[blockIdx.x];
}

__global__ void scatter_kernel(const int* __restrict__ src, const int* __restrict__ dst) {
    int e = blockIdx.x * blockDim.x + threadIdx.x;
    if (e >= N_EDGES) return;
    int d = dst[e];
    int p = atomicAdd(&g_hist[d], 1);
    g_srcp[p] = src[e];
    g_dstp[p] = d;
    g_Cp[p]   = g_C[e];
    g_dp[p]   = g_d[e];
}

__device__ __forceinline__ uint2 frag_of(const float* w, int k0, int n) {
    return make_uint2(f2h2(w[k0 * 128 + n], w[(k0 + 1) * 128 + n]),
                      f2h2(w[(k0 + 8) * 128 + n], w[(k0 + 9) * 128 + n]));
}
__global__ void build_frags_kernel(const float* __restrict__ mlp_w1,
                                   const float* __restrict__ mlp_w2,
                                   const float* __restrict__ conv_w2,
                                   const float* __restrict__ lin_w,
                                   const float* __restrict__ conv_w1,
                                   const float* __restrict__ out1_w,
                                   const float* __restrict__ out2_w) {
    int i = blockIdx.x * blockDim.x + threadIdx.x;
    if (i >= NLAYERS * 4096) return;
    int l = i / 4096, j = i % 4096;
    int lane = j & 31;
    int g_ = lane >> 2, t_ = lane & 3;
    {
        int kt = (j >> 5) & 7, nt = j >> 8;
        int k0 = kt * 16 + 2 * t_, n = nt * 8 + g_;
        g_w2f[l][j] = frag_of(mlp_w2 + (size_t)l * 16384, k0, n);
        g_wAf[l][j] = frag_of(conv_w2 + (size_t)l * 16384, k0, n);
        g_wBf[l][j] = frag_of(lin_w + (size_t)l * 16384, k0, n);
        g_wCf[l][j] = frag_of(conv_w1 + (size_t)l * 16384, k0, n);
        if (l == 0) {
            g_wO1f[j] = frag_of(out1_w, k0, n);
            g_wO2f[j] = frag_of(out2_w, k0, n);
        }
    }
    if (j < 2048) {
        int kt = (j >> 5) & 3, nt = j >> 7;
        int k0 = kt * 16 + 2 * t_, n = nt * 8 + g_;
        const float* w1 = mlp_w1 + (size_t)l * GDIM * 128;
        float v0 = (k0     < GDIM) ? w1[k0 * 128 + n]       : 0.f;
        float v1 = (k0 + 1 < GDIM) ? w1[(k0 + 1) * 128 + n] : 0.f;
        float v2 = (k0 + 8 < GDIM) ? w1[(k0 + 8) * 128 + n] : 0.f;
        float v3 = (k0 + 9 < GDIM) ? w1[(k0 + 9) * 128 + n] : 0.f;
        g_w1f[l][j] = make_uint2(f2h2(v0, v1), f2h2(v2, v3));
    }
}

// ---------------- initial xf = h @ conv_w1[0]  (fp16 MMA) -------------------
__global__ __launch_bounds__(256, 2) void xf0_kernel() {
    extern __shared__ char smraw[];
    __half* in_s = (__half*)smraw;             // 34816
    uint2*  wf   = (uint2*)(smraw + 34816);    // 32768
    int tid = threadIdx.x;
    int wid = tid >> 5;
    int lid = tid & 31;
    int gid = lid >> 2;
    int tg  = lid & 3;
    int lrow = lid & 15;
    int lcol = (lid >> 4) << 3;

    for (int i = tid; i < 2048; i += 256)
        ((uint4*)wf)[i] = ((const uint4*)g_wCf[0])[i];

    int n0 = blockIdx.x * 128;
    for (int i = tid; i < 128 * 32; i += 256) {
        int r = i >> 5, c4 = i & 31;
        float4 v = make_float4(0.f, 0.f, 0.f, 0.f);
        if (n0 + r < N_NODES)
            v = ((const float4*)&g_h[(size_t)(n0 + r) * 128])[c4];
        *(uint2*)&in_s[r * HID_STR + c4 * 4] = make_uint2(f2h2(v.x, v.y), f2h2(v.z, v.w));
    }
    __syncthreads();

    int mbase = (wid & 3) * 32;
    int nb    = (wid >> 2) * 8;
    float4 acc[2][8];
    #pragma unroll
    for (int mi = 0; mi < 2; mi++)
        #pragma unroll
        for (int ni = 0; ni < 8; ni++)
            acc[mi][ni] = make_float4(0.f, 0.f, 0.f, 0.f);
    #pragma unroll
    for (int kt = 0; kt < 8; kt++) {
        uint32_t a0[4], a1[4];
        ldsm4(a0, &in_s[(mbase + lrow) * HID_STR + kt * 16 + lcol]);
        ldsm4(a1, &in_s[(mbase + 16 + lrow) * HID_STR + kt * 16 + lcol]);
        #pragma unroll
        for (int ni = 0; ni < 8; ni++) {
            uint2 b = wf[((nb + ni) * 8 + kt) * 32 + lid];
            mma16816(acc[0][ni], a0, b);
            mma16816(acc[1][ni], a1, b);
        }
    }
    #pragma unroll
    for (int mi = 0; mi < 2; mi++) {
        int ra = mbase + mi * 16 + gid;
        int rb = ra + 8;
        int na = n0 + ra, nbn = n0 + rb;
        #pragma unroll
        for (int ni = 0; ni < 8; ni++) {
            int c0 = (nb + ni) * 8 + 2 * tg;
            float4 v = acc[mi][ni];
            if (na < N_NODES)
                *(float2*)&g_xf[(size_t)na * 128 + c0] = make_float2(v.x, v.y);
            if (nbn < N_NODES)
                *(float2*)&g_xf[(size_t)nbn * 128 + c0] = make_float2(v.z, v.w);
        }
    }
}

// ---------------- fp16 MMA edge kernel (R14 config) ----------------
__global__ __launch_bounds__(256, 2) void edge_mma_kernel(
        int layer, const float* __restrict__ b1, const float* __restrict__ b2) {
    extern __shared__ char smraw[];
    __half* ea_s  = (__half*)smraw;                   // 18432
    __half* hid_s = (__half*)(smraw + 18432);         // 34816
    __half* msg_h = hid_s;                            // aliases hid (post-GEMM2)
    uint2*  w1f   = (uint2*)(smraw + 53248);          // 16384
    uint2*  w2f   = (uint2*)(smraw + 69632);          // 32768
    float*  b1_s  = (float*)(smraw + 102400);
    float*  b2_s  = b1_s + 128;
    float*  C_s   = b2_s + 128;
    int*    src_s = (int*)(C_s + 128);
    int*    dst_s = src_s + 128;

    int tid = threadIdx.x;
    int wid = tid >> 5;
    int lid = tid & 31;
    int gid = lid >> 2;
    int tg  = lid & 3;
    int lrow = lid & 15;
    int lcol = (lid >> 4) << 3;
    int strip = wid & 3;
    int half  = wid >> 2;
    int bar_id = 1 + strip;

    const float step  = CUTOFF / (GDIM - 1);
    const float inv_step = (GDIM - 1) / CUTOFF;
    const float coeff = -0.5f / (step * step);

    if (tid < 128) { b1_s[tid] = b1[tid]; b2_s[tid] = b2[tid]; }
    for (int i = tid; i < 1024; i += 256)
        ((uint4*)w1f)[i] = ((const uint4*)g_w1f[layer])[i];
    for (int i = tid; i < 2048; i += 256)
        ((uint4*)w2f)[i] = ((const uint4*)g_w2f[layer])[i];
    __syncthreads();

    int mbase = strip * 32;
    int nb    = half * 8;
    int rchunk = 2 * strip + half;
    int rr0 = rchunk * 16;

    int psrc = 0, pdst = 0;
    float pC = 0.f, pd = 0.f;
    int t = blockIdx.x;
    if (t < NTILES && tid < 128) {
        int e0 = t * EPT;
        psrc = g_srcp[e0 + tid];
        pdst = g_dstp[e0 + tid];
        pC   = g_Cp[e0 + tid];
        pd   = g_dp[e0 + tid];
    }

    for (; t < NTILES; t += gridDim.x) {
        if (tid < 128) {
            src_s[tid] = psrc; dst_s[tid] = pdst; C_s[tid] = pC;
            uint4 z4 = make_uint4(0, 0, 0, 0);
            #pragma unroll
            for (int j = 0; j < 8; j++)
                *(uint4*)&ea_s[tid * EA_STR + j * 8] = z4;
            int c0 = (int)rintf(pd * inv_step);
            #pragma unroll
            for (int k = -6; k <= 6; k++) {
                int c = c0 + k;
                if (c >= 0 && c < GDIM) {
                    float diff = pd - c * step;
                    ea_s[tid * EA_STR + c] = __float2half_rn(__expf(coeff * diff * diff));
                }
            }
        }
        __syncthreads();   // S1

        float4 acc[2][8];
        #pragma unroll
        for (int mi = 0; mi < 2; mi++)
            #pragma unroll
            for (int ni = 0; ni < 8; ni++)
                acc[mi][ni] = make_float4(0.f, 0.f, 0.f, 0.f);

        // GEMM1: K=64
        #pragma unroll
        for (int kt = 0; kt < 4; kt++) {
            uint32_t a0[4], a1[4];
            ldsm4(a0, &ea_s[(mbase + lrow) * EA_STR + kt * 16 + lcol]);
            ldsm4(a1, &ea_s[(mbase + 16 + lrow) * EA_STR + kt * 16 + lcol]);
            #pragma unroll
            for (int ni = 0; ni < 8; ni++) {
                uint2 b = w1f[((nb + ni) * 4 + kt) * 32 + lid];
                mma16816(acc[0][ni], a0, b);
                mma16816(acc[1][ni], a1, b);
            }
        }

        // ssp -> fp16 HID
        #pragma unroll
        for (int mi = 0; mi < 2; mi++) {
            int ra = mbase + mi * 16 + gid;
            int rb = ra + 8;
            #pragma unroll
            for (int ni = 0; ni < 8; ni++) {
                int c0 = (nb + ni) * 8 + 2 * tg;
                float4 v = acc[mi][ni];
                float ba = b1_s[c0], bb = b1_s[c0 + 1];
                *(uint32_t*)&hid_s[ra * HID_STR + c0] =
                    f2h2(sspf_fast(v.x + ba), sspf_fast(v.y + bb));
                *(uint32_t*)&hid_s[rb * HID_STR + c0] =
                    f2h2(sspf_fast(v.z + ba), sspf_fast(v.w + bb));
            }
        }
        PAIR_BAR(bar_id);   // P1

        int tn = t + gridDim.x;
        if (tn < NTILES && tid < 128) {
            int e0n = tn * EPT;
            psrc = g_srcp[e0n + tid];
            pdst = g_dstp[e0n + tid];
            pC   = g_Cp[e0n + tid];
            pd   = g_dp[e0n + tid];
        }

        #pragma unroll
        for (int mi = 0; mi < 2; mi++)
            #pragma unroll
            for (int ni = 0; ni < 8; ni++)
                acc[mi][ni] = make_float4(0.f, 0.f, 0.f, 0.f);

        // GEMM2: K=128
        #pragma unroll
        for (int kt = 0; kt < 8; kt++) {
            uint32_t a0[4], a1[4];
            ldsm4(a0, &hid_s[(mbase + lrow) * HID_STR + kt * 16 + lcol]);
            ldsm4(a1, &hid_s[(mbase + 16 + lrow) * HID_STR + kt * 16 + lcol]);
            #pragma unroll
            for (int ni = 0; ni < 8; ni++) {
                uint2 b = w2f[((nb + ni) * 8 + kt) * 32 + lid];
                mma16816(acc[0][ni], a0, b);
                mma16816(acc[1][ni], a1, b);
            }
        }
        PAIR_BAR(bar_id);   // P2

        // stage fp16 msg = (C2+b2)*C
        #pragma unroll
        for (int mi = 0; mi < 2; mi++) {
            int ra = mbase + mi * 16 + gid;
            int rb = ra + 8;
            float Ca = C_s[ra], Cb = C_s[rb];
            #pragma unroll
            for (int ni = 0; ni < 8; ni++) {
                int c0 = (nb + ni) * 8 + 2 * tg;
                float4 v = acc[mi][ni];
                float2 bv = *(const float2*)&b2_s[c0];
                *(uint32_t*)&msg_h[ra * HID_STR + c0] =
                    f2h2((v.x + bv.x) * Ca, (v.y + bv.y) * Ca);
                *(uint32_t*)&msg_h[rb * HID_STR + c0] =
                    f2h2((v.z + bv.x) * Cb, (v.w + bv.y) * Cb);
            }
        }
        PAIR_BAR(bar_id);   // P3

        // segmented reduce (fp32 xf gather, fp32 accumulate)
        {
            int cg = lid;
            float4 run = make_float4(0.f, 0.f, 0.f, 0.f);
            int cur = dst_s[rr0];
            #pragma unroll
            for (int j = 0; j < 16; j++) {
                int dd = dst_s[rr0 + j];
                uint2 mh = *(uint2*)&msg_h[(rr0 + j) * HID_STR + cg * 4];
                float2 m01 = __half22float2(*(__half2*)&mh.x);
                float2 m23 = __half22float2(*(__half2*)&mh.y);
                float4 xv = *(const float4*)&g_xf[(size_t)src_s[rr0 + j] * 128 + cg * 4];
                if (dd != cur) {
                    atomicAdd((float4*)&g_agg[(size_t)cur * 128 + cg * 4], run);
                    run = make_float4(0.f, 0.f, 0.f, 0.f);
                    cur = dd;
                }
                run.x += m01.x * xv.x; run.y += m01.y * xv.y;
                run.z += m23.x * xv.z; run.w += m23.y * xv.w;
            }
            atomicAdd((float4*)&g_agg[(size_t)cur * 128 + cg * 4], run);
        }
        __syncthreads();   // S2
    }
}

// ---------------- fused node kernel: 512 threads, 16 warps ------------------
// warp layout: strip = wid&3 (32 rows), nq = wid>>2 (32 cols = 4 n-tiles)
__global__ __launch_bounds__(512, 1) void node_fused_kernel(
        int layer, const float* __restrict__ bA, const float* __restrict__ bB,
        const float* __restrict__ bO1, const float* __restrict__ bO2,
        const int* __restrict__ batch, int do_c) {
    extern __shared__ char smraw[];
    __half* in_s = (__half*)smraw;                     // 34816
    __half* x_s  = (__half*)(smraw + 34816);           // 34816
    uint2*  wAf  = (uint2*)(smraw + 69632);
    uint2*  wBf  = (uint2*)(smraw + 102400);
    uint2*  wCf  = (uint2*)(smraw + 135168);
    uint2*  wDf  = (uint2*)(smraw + 167936);
    float*  bA_s = (float*)(smraw + 200704);
    float*  bB_s = bA_s + 128;
    float*  bO1_s = bB_s + 128;
    float*  bO2_s = bO1_s + 128;
    int*    batch_s = (int*)(bO2_s + 128);

    int tid = threadIdx.x;
    int wid = tid >> 5;
    int lid = tid & 31;
    int gid = lid >> 2;
    int tg  = lid & 3;
    int lrow = lid & 15;
    int lcol = (lid >> 4) << 3;
    int do_out = !do_c;

    int mbase = (wid & 3) * 32;     // m strip
    int nb    = (wid >> 2) * 4;     // 4 n-tiles (32 cols)

    if (tid < 128) {
        bA_s[tid] = bA[tid]; bB_s[tid] = bB[tid];
        if (do_out) { bO1_s[tid] = bO1[tid]; bO2_s[tid] = bO2[tid]; }
    }
    for (int i = tid; i < 2048; i += 512) {
        ((uint4*)wAf)[i] = ((const uint4*)g_wAf[layer])[i];
        ((uint4*)wBf)[i] = ((const uint4*)g_wBf[layer])[i];
        if (do_c) {
            ((uint4*)wCf)[i] = ((const uint4*)g_wCf[layer + 1])[i];
        } else {
            ((uint4*)wCf)[i] = ((const uint4*)g_wO1f)[i];
            ((uint4*)wDf)[i] = ((const uint4*)g_wO2f)[i];
        }
    }
    __syncthreads();

    for (int tile = blockIdx.x; tile < NODE_TILES; tile += gridDim.x) {
        int n0 = tile * 128;
        for (int i = tid; i < 128 * 32; i += 512) {
            int r = i >> 5, c4 = i & 31;
            float4 v = make_float4(0.f, 0.f, 0.f, 0.f);
            if (n0 + r < N_NODES) {
                v = ((const float4*)&g_agg[(size_t)(n0 + r) * 128])[c4];
                ((float4*)&g_agg[(size_t)(n0 + r) * 128])[c4] =
                    make_float4(0.f, 0.f, 0.f, 0.f);
            }
            *(uint2*)&in_s[r * HID_STR + c4 * 4] = make_uint2(f2h2(v.x, v.y), f2h2(v.z, v.w));
        }
        if (do_out && tid < 128)
            batch_s[tid] = (n0 + tid < N_NODES) ? batch[n0 + tid] : 0;
        __syncthreads();

        float4 acc[2][4];
        // ---- GEMM A: x = ssp(agg @ wA + bA) ----
        #pragma unroll
        for (int mi = 0; mi < 2; mi++)
            #pragma unroll
            for (int ni = 0; ni < 4; ni++)
                acc[mi][ni] = make_float4(0.f, 0.f, 0.f, 0.f);
        #pragma unroll
        for (int kt = 0; kt < 8; kt++) {
            uint32_t a0[4], a1[4];
            ldsm4(a0, &in_s[(mbase + lrow) * HID_STR + kt * 16 + lcol]);
            ldsm4(a1, &in_s[(mbase + 16 + lrow) * HID_STR + kt * 16 + lcol]);
            #pragma unroll
            for (int ni = 0; ni < 4; ni++) {
                uint2 b = wAf[((nb + ni) * 8 + kt) * 32 + lid];
                mma16816(acc[0][ni], a0, b);
                mma16816(acc[1][ni], a1, b);
            }
        }
        #pragma unroll
        for (int mi = 0; mi < 2; mi++) {
            int ra = mbase + mi * 16 + gid;
            int rb = ra + 8;
            #pragma unroll
            for (int ni = 0; ni < 4; ni++) {
                int c0 = (nb + ni) * 8 + 2 * tg;
                float4 v = acc[mi][ni];
                float ba = bA_s[c0], bb = bA_s[c0 + 1];
                *(uint32_t*)&x_s[ra * HID_STR + c0] =
                    f2h2(sspf_fast(v.x + ba), sspf_fast(v.y + bb));
                *(uint32_t*)&x_s[rb * HID_STR + c0] =
                    f2h2(sspf_fast(v.z + ba), sspf_fast(v.w + bb));
            }
        }
        __syncthreads();

        // ---- GEMM B: h += x @ wB + bB ----
        #pragma unroll
        for (int mi = 0; mi < 2; mi++)
            #pragma unroll
            for (int ni = 0; ni < 4; ni++)
                acc[mi][ni] = make_float4(0.f, 0.f, 0.f, 0.f);
        #pragma unroll
        for (int kt = 0; kt < 8; kt++) {
            uint32_t a0[4], a1[4];
            ldsm4(a0, &x_s[(mbase + lrow) * HID_STR + kt * 16 + lcol]);
            ldsm4(a1, &x_s[(mbase + 16 + lrow) * HID_STR + kt * 16 + lcol]);
            #pragma unroll
            for (int ni = 0; ni < 4; ni++) {
                uint2 b = wBf[((nb + ni) * 8 + kt) * 32 + lid];
                mma16816(acc[0][ni], a0, b);
                mma16816(acc[1][ni], a1, b);
            }
        }
        #pragma unroll
        for (int mi = 0; mi < 2; mi++) {
            int ra = mbase + mi * 16 + gid;
            int rb = ra + 8;
            int na = n0 + ra, nbn = n0 + rb;
            #pragma unroll
            for (int ni = 0; ni < 4; ni++) {
                int c0 = (nb + ni) * 8 + 2 * tg;
                float4 v = acc[mi][ni];
                float ba = bB_s[c0], bb = bB_s[c0 + 1];
                float hx = 0.f, hy = 0.f, hz = 0.f, hw = 0.f;
                if (na < N_NODES) {
                    float2 hv = *(float2*)&g_h[(size_t)na * 128 + c0];
                    hx = hv.x + v.x + ba;
                    hy = hv.y + v.y + bb;
                    *(float2*)&g_h[(size_t)na * 128 + c0] = make_float2(hx, hy);
                }
                if (nbn < N_NODES) {
                    float2 hv = *(float2*)&g_h[(size_t)nbn * 128 + c0];
                    hz = hv.x + v.z + ba;
                    hw = hv.y + v.w + bb;
                    *(float2*)&g_h[(size_t)nbn * 128 + c0] = make_float2(hz, hw);
                }
                *(uint32_t*)&in_s[ra * HID_STR + c0] = f2h2(hx, hy);
                *(uint32_t*)&in_s[rb * HID_STR + c0] = f2h2(hz, hw);
            }
        }
        __syncthreads();

        if (do_c) {
            // ---- GEMM C: xf = h @ wC ----
            #pragma unroll
            for (int mi = 0; mi < 2; mi++)
                #pragma unroll
                for (int ni = 0; ni < 4; ni++)
                    acc[mi][ni] = make_float4(0.f, 0.f, 0.f, 0.f);
            #pragma unroll
            for (int kt = 0; kt < 8; kt++) {
                uint32_t a0[4], a1[4];
                ldsm4(a0, &in_s[(mbase + lrow) * HID_STR + kt * 16 + lcol]);
                ldsm4(a1, &in_s[(mbase + 16 + lrow) * HID_STR + kt * 16 + lcol]);
                #pragma unroll
                for (int ni = 0; ni < 4; ni++) {
                    uint2 b = wCf[((nb + ni) * 8 + kt) * 32 + lid];
                    mma16816(acc[0][ni], a0, b);
                    mma16816(acc[1][ni], a1, b);
                }
            }
            #pragma unroll
            for (int mi = 0; mi < 2; mi++) {
                int ra = mbase + mi * 16 + gid;
                int rb = ra + 8;
                int na = n0 + ra, nbn = n0 + rb;
                #pragma unroll
                for (int ni = 0; ni < 4; ni++) {
                    int c0 = (nb + ni) * 8 + 2 * tg;
                    float4 v = acc[mi][ni];
                    if (na < N_NODES)
                        *(float2*)&g_xf[(size_t)na * 128 + c0] = make_float2(v.x, v.y);
                    if (nbn < N_NODES)
                        *(float2*)&g_xf[(size_t)nbn * 128 + c0] = make_float2(v.z, v.w);
                }
            }
        } else {
            // ---- output head: x = ssp(h @ out1 + bO1) ----
            #pragma unroll
            for (int mi = 0; mi < 2; mi++)
                #pragma unroll
                for (int ni = 0; ni < 4; ni++)
                    acc[mi][ni] = make_float4(0.f, 0.f, 0.f, 0.f);
            #pragma unroll
            for (int kt = 0; kt < 8; kt++) {
                uint32_t a0[4], a1[4];
                ldsm4(a0, &in_s[(mbase + lrow) * HID_STR + kt * 16 + lcol]);
                ldsm4(a1, &in_s[(mbase + 16 + lrow) * HID_STR + kt * 16 + lcol]);
                #pragma unroll
                for (int ni = 0; ni < 4; ni++) {
                    uint2 b = wCf[((nb + ni) * 8 + kt) * 32 + lid];
                    mma16816(acc[0][ni], a0, b);
                    mma16816(acc[1][ni], a1, b);
                }
            }
            #pragma unroll
            for (int mi = 0; mi < 2; mi++) {
                int ra = mbase + mi * 16 + gid;
                int rb = ra + 8;
                #pragma unroll
                for (int ni = 0; ni < 4; ni++) {
                    int c0 = (nb + ni) * 8 + 2 * tg;
                    float4 v = acc[mi][ni];
                    float ba = bO1_s[c0], bb = bO1_s[c0 + 1];
                    *(uint32_t*)&x_s[ra * HID_STR + c0] =
                        f2h2(sspf_fast(v.x + ba), sspf_fast(v.y + bb));
                    *(uint32_t*)&x_s[rb * HID_STR + c0] =
                        f2h2(sspf_fast(v.z + ba), sspf_fast(v.w + bb));
                }
            }
            __syncthreads();

            // ---- output head: out = x @ out2 + bO2 -> g_sums[batch] ----
            #pragma unroll
            for (int mi = 0; mi < 2; mi++)
                #pragma unroll
                for (int ni = 0; ni < 4; ni++)
                    acc[mi][ni] = make_float4(0.f, 0.f, 0.f, 0.f);
            #pragma unroll
            for (int kt = 0; kt < 8; kt++) {
                uint32_t a0[4], a1[4];
                ldsm4(a0, &x_s[(mbase + lrow) * HID_STR + kt * 16 + lcol]);
                ldsm4(a1, &x_s[(mbase + 16 + lrow) * HID_STR + kt * 16 + lcol]);
                #pragma unroll
                for (int ni = 0; ni < 4; ni++) {
                    uint2 b = wDf[((nb + ni) * 8 + kt) * 32 + lid];
                    mma16816(acc[0][ni], a0, b);
                    mma16816(acc[1][ni], a1, b);
                }
            }
            #pragma unroll
            for (int mi = 0; mi < 2; mi++) {
                int ra = mbase + mi * 16 + gid;
                int rb = ra + 8;
                int na = n0 + ra, nbn = n0 + rb;
                #pragma unroll
                for (int ni = 0; ni < 4; ni++) {
                    int c0 = (nb + ni) * 8 + 2 * tg;
                    float4 v = acc[mi][ni];
                    float2 bv = *(const float2*)&bO2_s[c0];
                    if (na < N_NODES) {
                        float2 o = make_float2(v.x + bv.x, v.y + bv.y);
                        atomicAdd((float2*)&g_sums[batch_s[ra] * 128 + c0], o);
                    }
                    if (nbn < N_NODES) {
                        float2 o = make_float2(v.z + bv.x, v.w + bv.y);
                        atomicAdd((float2*)&g_sums[batch_s[rb] * 128 + c0], o);
                    }
                }
            }
        }
        __syncthreads();
    }
}

__global__ void finalize_kernel(float* __restrict__ out) {
    int i = blockIdx.x * blockDim.x + threadIdx.x;
    if (i >= NGRAPH * HDIM) return;
    out[i] = g_sums[i] / fmaxf(g_cnt[i >> 7], 1.0f);
}

// ---------------- launcher ----------------
extern "C" void kernel_launch(void* const* d_in, const int* in_sizes, int n_in,
                              void* d_out, int out_size) {
    const int*   z       = (const int*)d_in[0];
    const float* pos     = (const float*)d_in[1];
    const int*   ei      = (const int*)d_in[2];
    const int*   batch   = (const int*)d_in[3];
    const float* emb     = (const float*)d_in[4];
    const float* mlp_w1  = (const float*)d_in[5];
    const float* mlp_b1  = (const float*)d_in[6];
    const float* mlp_w2  = (const float*)d_in[7];
    const float* mlp_b2  = (const float*)d_in[8];
    const float* conv_w1 = (const float*)d_in[9];
    const float* conv_w2 = (const float*)d_in[10];
    const float* conv_b2 = (const float*)d_in[11];
    const float* lin_w   = (const float*)d_in[12];
    const float* lin_b   = (const float*)d_in[13];
    const float* out1_w  = (const float*)d_in[14];
    const float* out1_b  = (const float*)d_in[15];
    const float* out2_w  = (const float*)d_in[16];
    const float* out2_b  = (const float*)d_in[17];
    float* out = (float*)d_out;

    const int* src = ei;
    const int* dst = ei + N_EDGES;

    const int EDGE_SMEM = 104960;
    const int NODE_SMEM = 203264;
    const int XF0_SMEM  = 67584;

    cudaFuncSetAttribute(edge_mma_kernel, cudaFuncAttributeMaxDynamicSharedMemorySize, EDGE_SMEM);
    cudaFuncSetAttribute(node_fused_kernel, cudaFuncAttributeMaxDynamicSharedMemorySize, NODE_SMEM);
    cudaFuncSetAttribute(xf0_kernel, cudaFuncAttributeMaxDynamicSharedMemorySize, XF0_SMEM);

    zero_all_kernel<<<(N_NODES * HDIM + 255) / 256, 256>>>();
    init_h_kernel<<<(N_NODES * HDIM + 255) / 256, 256>>>(z, emb, batch);
    dist_hist_kernel<<<(N_EDGES + 255) / 256, 256>>>(src, dst, pos);
    scan1_kernel<<<SCAN_BLOCKS, 1024>>>();
    scan2_kernel<<<1, 32>>>();
    scan3_kernel<<<SCAN_BLOCKS, 1024>>>();
    scatter_kernel<<<(N_EDGES + 255) / 256, 256>>>(src, dst);
    build_frags_kernel<<<(NLAYERS * 4096 + 255) / 256, 256>>>(
        mlp_w1, mlp_w2, conv_w2, lin_w, conv_w1, out1_w, out2_w);

    xf0_kernel<<<NODE_TILES, 256, XF0_SMEM>>>();   // xf for layer 0

    for (int l = 0; l < NLAYERS; l++) {
        edge_mma_kernel<<<296, 256, EDGE_SMEM>>>(
            l, mlp_b1 + (size_t)l * 128, mlp_b2 + (size_t)l * 128);
        int do_c = (l < NLAYERS - 1) ? 1 : 0;
        node_fused_kernel<<<148, 512, NODE_SMEM>>>(
            l, conv_b2 + (size_t)l * 128, lin_b + (size_t)l * 128,
            out1_b, out2_b, batch, do_c);
    }

    finalize_kernel<<<(NGRAPH * HDIM + 255) / 256, 256>>>(out);
}

// round 17
// speedup vs baseline: 1.0981x; 1.0175x over previous
#include <cuda_runtime.h>
#include <cuda_fp16.h>
#include <math.h>
#include <stdint.h>

#define N_NODES 20000
#define N_EDGES 640000
#define HDIM    128
#define GDIM    50
#define NLAYERS 6
#define NGRAPH  64
#define CUTOFF  10.0f
#define LOG2F_  0.69314718055994531f
#define PI_     3.14159265358979323846f

#define EPT     128
#define NTILES  (N_EDGES / EPT)
#define EA_STR  72
#define HID_STR 136
#define NODE_TILES ((N_NODES + 127) / 128)      // 157 (last layer)
#define MID_TILES  ((N_NODES + 191) / 192)      // 105 (single wave)
#define SCAN_BLOCKS ((N_NODES + 1023) / 1024)   // 20

// ---------------- device scratch ----------------
static __device__ __align__(16) float  g_h[N_NODES * HDIM];
static __device__ __align__(16) float  g_xf[N_NODES * HDIM];
static __device__ __align__(16) float  g_agg[N_NODES * HDIM];
static __device__ __align__(16) float  g_d[N_EDGES];
static __device__ __align__(16) float  g_C[N_EDGES];
static __device__ __align__(16) float  g_sums[NGRAPH * HDIM];
static __device__ float g_cnt[NGRAPH];
static __device__ int   g_hist[N_NODES];
static __device__ int   g_bsum[SCAN_BLOCKS];
static __device__ int   g_srcp[N_EDGES];
static __device__ int   g_dstp[N_EDGES];
static __device__ float g_Cp[N_EDGES];
static __device__ float g_dp[N_EDGES];
// prebuilt fp16 B-fragments (m16n8k16 layout)
static __device__ __align__(16) uint2 g_w1f[NLAYERS][2048];
static __device__ __align__(16) uint2 g_w2f[NLAYERS][4096];
static __device__ __align__(16) uint2 g_wAf[NLAYERS][4096];
static __device__ __align__(16) uint2 g_wBf[NLAYERS][4096];
static __device__ __align__(16) uint2 g_wCf[NLAYERS][4096];
static __device__ __align__(16) uint2 g_wO1f[4096];
static __device__ __align__(16) uint2 g_wO2f[4096];

// ---------------- helpers ----------------
__device__ __forceinline__ float sspf_fast(float x) {
    return fmaxf(x, 0.f) + __logf(1.f + __expf(-fabsf(x))) - LOG2F_;
}
__device__ __forceinline__ uint32_t smem_u32(const void* p) {
    uint32_t a;
    asm("{ .reg .u64 t; cvta.to.shared.u64 t, %1; cvt.u32.u64 %0, t; }" : "=r"(a) : "l"(p));
    return a;
}
__device__ __forceinline__ uint32_t f2h2(float lo, float hi) {
    __half2 h = __floats2half2_rn(lo, hi);
    return *reinterpret_cast<uint32_t*>(&h);
}
__device__ __forceinline__ void mma16816(float4& d, const uint32_t a[4], uint2 b) {
    asm volatile(
        "mma.sync.aligned.m16n8k16.row.col.f32.f16.f16.f32 "
        "{%0,%1,%2,%3}, {%4,%5,%6,%7}, {%8,%9}, {%0,%1,%2,%3};\n"
        : "+f"(d.x), "+f"(d.y), "+f"(d.z), "+f"(d.w)
        : "r"(a[0]), "r"(a[1]), "r"(a[2]), "r"(a[3]), "r"(b.x), "r"(b.y));
}
__device__ __forceinline__ void ldsm4(uint32_t r[4], const void* p) {
    uint32_t a = smem_u32(p);
    asm volatile("ldmatrix.sync.aligned.m8n8.x4.shared.b16 {%0,%1,%2,%3}, [%4];"
        : "=r"(r[0]), "=r"(r[1]), "=r"(r[2]), "=r"(r[3]) : "r"(a));
}
#define PAIR_BAR(id) asm volatile("bar.sync %0, 64;" :: "r"(id) : "memory")

// ---------------- precompute ----------------
__global__ void zero_all_kernel() {
    int i = blockIdx.x * blockDim.x + threadIdx.x;
    if (i < N_NODES * HDIM) g_agg[i] = 0.f;
    if (i < N_NODES) g_hist[i] = 0;
    if (i < NGRAPH * HDIM) g_sums[i] = 0.f;
    if (i < NGRAPH) g_cnt[i] = 0.f;
}

__global__ void init_h_kernel(const int* __restrict__ z, const float* __restrict__ emb,
                              const int* __restrict__ batch) {
    int i = blockIdx.x * blockDim.x + threadIdx.x;
    if (i >= N_NODES * HDIM) return;
    int n = i >> 7, j = i & 127;
    g_h[i] = emb[z[n] * HDIM + j];
    if (j == 0) atomicAdd(&g_cnt[batch[n]], 1.0f);
}

__global__ void dist_hist_kernel(const int* __restrict__ src, const int* __restrict__ dst,
                                 const float* __restrict__ pos) {
    int e = blockIdx.x * blockDim.x + threadIdx.x;
    if (e >= N_EDGES) return;
    int s = src[e], t = dst[e];
    float dx = pos[s * 3 + 0] - pos[t * 3 + 0];
    float dy = pos[s * 3 + 1] - pos[t * 3 + 1];
    float dz = pos[s * 3 + 2] - pos[t * 3 + 2];
    float d = sqrtf(dx * dx + dy * dy + dz * dz);
    g_d[e] = d;
    g_C[e] = 0.5f * (cosf(d * (PI_ / CUTOFF)) + 1.0f);
    atomicAdd(&g_hist[t], 1);
}

__global__ void scan1_kernel() {
    __shared__ int s[1024];
    int t = threadIdx.x;
    int idx = blockIdx.x * 1024 + t;
    int v = (idx < N_NODES) ? g_hist[idx] : 0;
    s[t] = v;
    __syncthreads();
    for (int off = 512; off > 0; off >>= 1) {
        if (t < off) s[t] += s[t + off];
        __syncthreads();
    }
    if (t == 0) g_bsum[blockIdx.x] = s[0];
}
__global__ void scan2_kernel() {
    if (threadIdx.x == 0) {
        int run = 0;
        for (int b = 0; b < SCAN_BLOCKS; b++) {
            int c = g_bsum[b];
            g_bsum[b] = run;
            run += c;
        }
    }
}
__global__ void scan3_kernel() {
    __shared__ int s[1024];
    int t = threadIdx.x;
    int idx = blockIdx.x * 1024 + t;
    int v = (idx < N_NODES) ? g_hist[idx] : 0;
    s[t] = v;
    __syncthreads();
    for (int off = 1; off < 1024; off <<= 1) {
        int u = (t >= off) ? s[t - off] : 0;
        __syncthreads();
        s[t] += u;
        __syncthreads();
    }
    if (idx < N_NODES) g_hist[idx] = s[t] - v + g_bsum[blockIdx.x];
}

__global__ void scatter_kernel(const int* __restrict__ src, const int* __restrict__ dst) {
    int e = blockIdx.x * blockDim.x + threadIdx.x;
    if (e >= N_EDGES) return;
    int d = dst[e];
    int p = atomicAdd(&g_hist[d], 1);
    g_srcp[p] = src[e];
    g_dstp[p] = d;
    g_Cp[p]   = g_C[e];
    g_dp[p]   = g_d[e];
}

__device__ __forceinline__ uint2 frag_of(const float* w, int k0, int n) {
    return make_uint2(f2h2(w[k0 * 128 + n], w[(k0 + 1) * 128 + n]),
                      f2h2(w[(k0 + 8) * 128 + n], w[(k0 + 9) * 128 + n]));
}
__global__ void build_frags_kernel(const float* __restrict__ mlp_w1,
                                   const float* __restrict__ mlp_w2,
                                   const float* __restrict__ conv_w2,
                                   const float* __restrict__ lin_w,
                                   const float* __restrict__ conv_w1,
                                   const float* __restrict__ out1_w,
                                   const float* __restrict__ out2_w) {
    int i = blockIdx.x * blockDim.x + threadIdx.x;
    if (i >= NLAYERS * 4096) return;
    int l = i / 4096, j = i % 4096;
    int lane = j & 31;
    int g_ = lane >> 2, t_ = lane & 3;
    {
        int kt = (j >> 5) & 7, nt = j >> 8;
        int k0 = kt * 16 + 2 * t_, n = nt * 8 + g_;
        g_w2f[l][j] = frag_of(mlp_w2 + (size_t)l * 16384, k0, n);
        g_wAf[l][j] = frag_of(conv_w2 + (size_t)l * 16384, k0, n);
        g_wBf[l][j] = frag_of(lin_w + (size_t)l * 16384, k0, n);
        g_wCf[l][j] = frag_of(conv_w1 + (size_t)l * 16384, k0, n);
        if (l == 0) {
            g_wO1f[j] = frag_of(out1_w, k0, n);
            g_wO2f[j] = frag_of(out2_w, k0, n);
        }
    }
    if (j < 2048) {
        int kt = (j >> 5) & 3, nt = j >> 7;
        int k0 = kt * 16 + 2 * t_, n = nt * 8 + g_;
        const float* w1 = mlp_w1 + (size_t)l * GDIM * 128;
        float v0 = (k0     < GDIM) ? w1[k0 * 128 + n]       : 0.f;
        float v1 = (k0 + 1 < GDIM) ? w1[(k0 + 1) * 128 + n] : 0.f;
        float v2 = (k0 + 8 < GDIM) ? w1[(k0 + 8) * 128 + n] : 0.f;
        float v3 = (k0 + 9 < GDIM) ? w1[(k0 + 9) * 128 + n] : 0.f;
        g_w1f[l][j] = make_uint2(f2h2(v0, v1), f2h2(v2, v3));
    }
}

// ---------------- initial xf = h @ conv_w1[0]  (fp16 MMA) -------------------
__global__ __launch_bounds__(256, 2) void xf0_kernel() {
    extern __shared__ char smraw[];
    __half* in_s = (__half*)smraw;             // 34816
    uint2*  wf   = (uint2*)(smraw + 34816);    // 32768
    int tid = threadIdx.x;
    int wid = tid >> 5;
    int lid = tid & 31;
    int gid = lid >> 2;
    int tg  = lid & 3;
    int lrow = lid & 15;
    int lcol = (lid >> 4) << 3;

    for (int i = tid; i < 2048; i += 256)
        ((uint4*)wf)[i] = ((const uint4*)g_wCf[0])[i];

    int n0 = blockIdx.x * 128;
    for (int i = tid; i < 128 * 32; i += 256) {
        int r = i >> 5, c4 = i & 31;
        float4 v = make_float4(0.f, 0.f, 0.f, 0.f);
        if (n0 + r < N_NODES)
            v = ((const float4*)&g_h[(size_t)(n0 + r) * 128])[c4];
        *(uint2*)&in_s[r * HID_STR + c4 * 4] = make_uint2(f2h2(v.x, v.y), f2h2(v.z, v.w));
    }
    __syncthreads();

    int mbase = (wid & 3) * 32;
    int nb    = (wid >> 2) * 8;
    float4 acc[2][8];
    #pragma unroll
    for (int mi = 0; mi < 2; mi++)
        #pragma unroll
        for (int ni = 0; ni < 8; ni++)
            acc[mi][ni] = make_float4(0.f, 0.f, 0.f, 0.f);
    #pragma unroll
    for (int kt = 0; kt < 8; kt++) {
        uint32_t a0[4], a1[4];
        ldsm4(a0, &in_s[(mbase + lrow) * HID_STR + kt * 16 + lcol]);
        ldsm4(a1, &in_s[(mbase + 16 + lrow) * HID_STR + kt * 16 + lcol]);
        #pragma unroll
        for (int ni = 0; ni < 8; ni++) {
            uint2 b = wf[((nb + ni) * 8 + kt) * 32 + lid];
            mma16816(acc[0][ni], a0, b);
            mma16816(acc[1][ni], a1, b);
        }
    }
    #pragma unroll
    for (int mi = 0; mi < 2; mi++) {
        int ra = mbase + mi * 16 + gid;
        int rb = ra + 8;
        int na = n0 + ra, nbn = n0 + rb;
        #pragma unroll
        for (int ni = 0; ni < 8; ni++) {
            int c0 = (nb + ni) * 8 + 2 * tg;
            float4 v = acc[mi][ni];
            if (na < N_NODES)
                *(float2*)&g_xf[(size_t)na * 128 + c0] = make_float2(v.x, v.y);
            if (nbn < N_NODES)
                *(float2*)&g_xf[(size_t)nbn * 128 + c0] = make_float2(v.z, v.w);
        }
    }
}

// ---------------- fp16 MMA edge kernel (R14/R16 config) ----------------
__global__ __launch_bounds__(256, 2) void edge_mma_kernel(
        int layer, const float* __restrict__ b1, const float* __restrict__ b2) {
    extern __shared__ char smraw[];
    __half* ea_s  = (__half*)smraw;                   // 18432
    __half* hid_s = (__half*)(smraw + 18432);         // 34816
    __half* msg_h = hid_s;                            // aliases hid (post-GEMM2)
    uint2*  w1f   = (uint2*)(smraw + 53248);          // 16384
    uint2*  w2f   = (uint2*)(smraw + 69632);          // 32768
    float*  b1_s  = (float*)(smraw + 102400);
    float*  b2_s  = b1_s + 128;
    float*  C_s   = b2_s + 128;
    int*    src_s = (int*)(C_s + 128);
    int*    dst_s = src_s + 128;

    int tid = threadIdx.x;
    int wid = tid >> 5;
    int lid = tid & 31;
    int gid = lid >> 2;
    int tg  = lid & 3;
    int lrow = lid & 15;
    int lcol = (lid >> 4) << 3;
    int strip = wid & 3;
    int half  = wid >> 2;
    int bar_id = 1 + strip;

    const float step  = CUTOFF / (GDIM - 1);
    const float inv_step = (GDIM - 1) / CUTOFF;
    const float coeff = -0.5f / (step * step);

    if (tid < 128) { b1_s[tid] = b1[tid]; b2_s[tid] = b2[tid]; }
    for (int i = tid; i < 1024; i += 256)
        ((uint4*)w1f)[i] = ((const uint4*)g_w1f[layer])[i];
    for (int i = tid; i < 2048; i += 256)
        ((uint4*)w2f)[i] = ((const uint4*)g_w2f[layer])[i];
    __syncthreads();

    int mbase = strip * 32;
    int nb    = half * 8;
    int rchunk = 2 * strip + half;
    int rr0 = rchunk * 16;

    int psrc = 0, pdst = 0;
    float pC = 0.f, pd = 0.f;
    int t = blockIdx.x;
    if (t < NTILES && tid < 128) {
        int e0 = t * EPT;
        psrc = g_srcp[e0 + tid];
        pdst = g_dstp[e0 + tid];
        pC   = g_Cp[e0 + tid];
        pd   = g_dp[e0 + tid];
    }

    for (; t < NTILES; t += gridDim.x) {
        if (tid < 128) {
            src_s[tid] = psrc; dst_s[tid] = pdst; C_s[tid] = pC;
            uint4 z4 = make_uint4(0, 0, 0, 0);
            #pragma unroll
            for (int j = 0; j < 8; j++)
                *(uint4*)&ea_s[tid * EA_STR + j * 8] = z4;
            int c0 = (int)rintf(pd * inv_step);
            #pragma unroll
            for (int k = -6; k <= 6; k++) {
                int c = c0 + k;
                if (c >= 0 && c < GDIM) {
                    float diff = pd - c * step;
                    ea_s[tid * EA_STR + c] = __float2half_rn(__expf(coeff * diff * diff));
                }
            }
        }
        __syncthreads();   // S1

        float4 acc[2][8];
        #pragma unroll
        for (int mi = 0; mi < 2; mi++)
            #pragma unroll
            for (int ni = 0; ni < 8; ni++)
                acc[mi][ni] = make_float4(0.f, 0.f, 0.f, 0.f);

        // GEMM1: K=64
        #pragma unroll
        for (int kt = 0; kt < 4; kt++) {
            uint32_t a0[4], a1[4];
            ldsm4(a0, &ea_s[(mbase + lrow) * EA_STR + kt * 16 + lcol]);
            ldsm4(a1, &ea_s[(mbase + 16 + lrow) * EA_STR + kt * 16 + lcol]);
            #pragma unroll
            for (int ni = 0; ni < 8; ni++) {
                uint2 b = w1f[((nb + ni) * 4 + kt) * 32 + lid];
                mma16816(acc[0][ni], a0, b);
                mma16816(acc[1][ni], a1, b);
            }
        }

        // ssp -> fp16 HID
        #pragma unroll
        for (int mi = 0; mi < 2; mi++) {
            int ra = mbase + mi * 16 + gid;
            int rb = ra + 8;
            #pragma unroll
            for (int ni = 0; ni < 8; ni++) {
                int c0 = (nb + ni) * 8 + 2 * tg;
                float4 v = acc[mi][ni];
                float ba = b1_s[c0], bb = b1_s[c0 + 1];
                *(uint32_t*)&hid_s[ra * HID_STR + c0] =
                    f2h2(sspf_fast(v.x + ba), sspf_fast(v.y + bb));
                *(uint32_t*)&hid_s[rb * HID_STR + c0] =
                    f2h2(sspf_fast(v.z + ba), sspf_fast(v.w + bb));
            }
        }
        PAIR_BAR(bar_id);   // P1

        int tn = t + gridDim.x;
        if (tn < NTILES && tid < 128) {
            int e0n = tn * EPT;
            psrc = g_srcp[e0n + tid];
            pdst = g_dstp[e0n + tid];
            pC   = g_Cp[e0n + tid];
            pd   = g_dp[e0n + tid];
        }

        #pragma unroll
        for (int mi = 0; mi < 2; mi++)
            #pragma unroll
            for (int ni = 0; ni < 8; ni++)
                acc[mi][ni] = make_float4(0.f, 0.f, 0.f, 0.f);

        // GEMM2: K=128
        #pragma unroll
        for (int kt = 0; kt < 8; kt++) {
            uint32_t a0[4], a1[4];
            ldsm4(a0, &hid_s[(mbase + lrow) * HID_STR + kt * 16 + lcol]);
            ldsm4(a1, &hid_s[(mbase + 16 + lrow) * HID_STR + kt * 16 + lcol]);
            #pragma unroll
            for (int ni = 0; ni < 8; ni++) {
                uint2 b = w2f[((nb + ni) * 8 + kt) * 32 + lid];
                mma16816(acc[0][ni], a0, b);
                mma16816(acc[1][ni], a1, b);
            }
        }
        PAIR_BAR(bar_id);   // P2

        // stage fp16 msg = (C2+b2)*C
        #pragma unroll
        for (int mi = 0; mi < 2; mi++) {
            int ra = mbase + mi * 16 + gid;
            int rb = ra + 8;
            float Ca = C_s[ra], Cb = C_s[rb];
            #pragma unroll
            for (int ni = 0; ni < 8; ni++) {
                int c0 = (nb + ni) * 8 + 2 * tg;
                float4 v = acc[mi][ni];
                float2 bv = *(const float2*)&b2_s[c0];
                *(uint32_t*)&msg_h[ra * HID_STR + c0] =
                    f2h2((v.x + bv.x) * Ca, (v.y + bv.y) * Ca);
                *(uint32_t*)&msg_h[rb * HID_STR + c0] =
                    f2h2((v.z + bv.x) * Cb, (v.w + bv.y) * Cb);
            }
        }
        PAIR_BAR(bar_id);   // P3

        // segmented reduce (fp32 xf gather, fp32 accumulate)
        {
            int cg = lid;
            float4 run = make_float4(0.f, 0.f, 0.f, 0.f);
            int cur = dst_s[rr0];
            #pragma unroll
            for (int j = 0; j < 16; j++) {
                int dd = dst_s[rr0 + j];
                uint2 mh = *(uint2*)&msg_h[(rr0 + j) * HID_STR + cg * 4];
                float2 m01 = __half22float2(*(__half2*)&mh.x);
                float2 m23 = __half22float2(*(__half2*)&mh.y);
                float4 xv = *(const float4*)&g_xf[(size_t)src_s[rr0 + j] * 128 + cg * 4];
                if (dd != cur) {
                    atomicAdd((float4*)&g_agg[(size_t)cur * 128 + cg * 4], run);
                    run = make_float4(0.f, 0.f, 0.f, 0.f);
                    cur = dd;
                }
                run.x += m01.x * xv.x; run.y += m01.y * xv.y;
                run.z += m23.x * xv.z; run.w += m23.y * xv.w;
            }
            atomicAdd((float4*)&g_agg[(size_t)cur * 128 + cg * 4], run);
        }
        __syncthreads();   // S2
    }
}

// ---------------- node kernel, mid layers: M=192, single wave ---------------
// 16 warps: strip = wid&3 (48 rows, 3 m-tiles), nq = wid>>2 (4 n-tiles)
__global__ __launch_bounds__(512, 1) void node_mid_kernel(
        int layer, const float* __restrict__ bA, const float* __restrict__ bB) {
    extern __shared__ char smraw[];
    __half* in_s = (__half*)smraw;                     // 192*136*2 = 52224
    __half* x_s  = (__half*)(smraw + 52224);           // 52224
    uint2*  wAf  = (uint2*)(smraw + 104448);           // 32768
    uint2*  wBf  = (uint2*)(smraw + 137216);           // 32768
    uint2*  wCf  = (uint2*)(smraw + 169984);           // 32768
    float*  bA_s = (float*)(smraw + 202752);           // 512
    float*  bB_s = bA_s + 128;                         // 512

    int tid = threadIdx.x;
    int wid = tid >> 5;
    int lid = tid & 31;
    int gid = lid >> 2;
    int tg  = lid & 3;
    int lrow = lid & 15;
    int lcol = (lid >> 4) << 3;

    int mbase = (wid & 3) * 48;     // 48-row strip
    int nb    = (wid >> 2) * 4;     // 4 n-tiles

    if (tid < 128) { bA_s[tid] = bA[tid]; bB_s[tid] = bB[tid]; }
    for (int i = tid; i < 2048; i += 512) {
        ((uint4*)wAf)[i] = ((const uint4*)g_wAf[layer])[i];
        ((uint4*)wBf)[i] = ((const uint4*)g_wBf[layer])[i];
        ((uint4*)wCf)[i] = ((const uint4*)g_wCf[layer + 1])[i];
    }
    __syncthreads();

    for (int tile = blockIdx.x; tile < MID_TILES; tile += gridDim.x) {
        int n0 = tile * 192;
        // stage agg -> fp16; zero agg
        for (int i = tid; i < 192 * 32; i += 512) {
            int r = i >> 5, c4 = i & 31;
            float4 v = make_float4(0.f, 0.f, 0.f, 0.f);
            if (n0 + r < N_NODES) {
                v = ((const float4*)&g_agg[(size_t)(n0 + r) * 128])[c4];
                ((float4*)&g_agg[(size_t)(n0 + r) * 128])[c4] =
                    make_float4(0.f, 0.f, 0.f, 0.f);
            }
            *(uint2*)&in_s[r * HID_STR + c4 * 4] = make_uint2(f2h2(v.x, v.y), f2h2(v.z, v.w));
        }
        __syncthreads();

        float4 acc[3][4];
        // ---- GEMM A: x = ssp(agg @ wA + bA) ----
        #pragma unroll
        for (int mi = 0; mi < 3; mi++)
            #pragma unroll
            for (int ni = 0; ni < 4; ni++)
                acc[mi][ni] = make_float4(0.f, 0.f, 0.f, 0.f);
        #pragma unroll
        for (int kt = 0; kt < 8; kt++) {
            uint32_t a0[4], a1[4], a2[4];
            ldsm4(a0, &in_s[(mbase + lrow) * HID_STR + kt * 16 + lcol]);
            ldsm4(a1, &in_s[(mbase + 16 + lrow) * HID_STR + kt * 16 + lcol]);
            ldsm4(a2, &in_s[(mbase + 32 + lrow) * HID_STR + kt * 16 + lcol]);
            #pragma unroll
            for (int ni = 0; ni < 4; ni++) {
                uint2 b = wAf[((nb + ni) * 8 + kt) * 32 + lid];
                mma16816(acc[0][ni], a0, b);
                mma16816(acc[1][ni], a1, b);
                mma16816(acc[2][ni], a2, b);
            }
        }
        #pragma unroll
        for (int mi = 0; mi < 3; mi++) {
            int ra = mbase + mi * 16 + gid;
            int rb = ra + 8;
            #pragma unroll
            for (int ni = 0; ni < 4; ni++) {
                int c0 = (nb + ni) * 8 + 2 * tg;
                float4 v = acc[mi][ni];
                float ba = bA_s[c0], bb = bA_s[c0 + 1];
                *(uint32_t*)&x_s[ra * HID_STR + c0] =
                    f2h2(sspf_fast(v.x + ba), sspf_fast(v.y + bb));
                *(uint32_t*)&x_s[rb * HID_STR + c0] =
                    f2h2(sspf_fast(v.z + ba), sspf_fast(v.w + bb));
            }
        }
        __syncthreads();

        // ---- GEMM B: h += x @ wB + bB ----
        #pragma unroll
        for (int mi = 0; mi < 3; mi++)
            #pragma unroll
            for (int ni = 0; ni < 4; ni++)
                acc[mi][ni] = make_float4(0.f, 0.f, 0.f, 0.f);
        #pragma unroll
        for (int kt = 0; kt < 8; kt++) {
            uint32_t a0[4], a1[4], a2[4];
            ldsm4(a0, &x_s[(mbase + lrow) * HID_STR + kt * 16 + lcol]);
            ldsm4(a1, &x_s[(mbase + 16 + lrow) * HID_STR + kt * 16 + lcol]);
            ldsm4(a2, &x_s[(mbase + 32 + lrow) * HID_STR + kt * 16 + lcol]);
            #pragma unroll
            for (int ni = 0; ni < 4; ni++) {
                uint2 b = wBf[((nb + ni) * 8 + kt) * 32 + lid];
                mma16816(acc[0][ni], a0, b);
                mma16816(acc[1][ni], a1, b);
                mma16816(acc[2][ni], a2, b);
            }
        }
        #pragma unroll
        for (int mi = 0; mi < 3; mi++) {
            int ra = mbase + mi * 16 + gid;
            int rb = ra + 8;
            int na = n0 + ra, nbn = n0 + rb;
            #pragma unroll
            for (int ni = 0; ni < 4; ni++) {
                int c0 = (nb + ni) * 8 + 2 * tg;
                float4 v = acc[mi][ni];
                float ba = bB_s[c0], bb = bB_s[c0 + 1];
                float hx = 0.f, hy = 0.f, hz = 0.f, hw = 0.f;
                if (na < N_NODES) {
                    float2 hv = *(float2*)&g_h[(size_t)na * 128 + c0];
                    hx = hv.x + v.x + ba;
                    hy = hv.y + v.y + bb;
                    *(float2*)&g_h[(size_t)na * 128 + c0] = make_float2(hx, hy);
                }
                if (nbn < N_NODES) {
                    float2 hv = *(float2*)&g_h[(size_t)nbn * 128 + c0];
                    hz = hv.x + v.z + ba;
                    hw = hv.y + v.w + bb;
                    *(float2*)&g_h[(size_t)nbn * 128 + c0] = make_float2(hz, hw);
                }
                *(uint32_t*)&in_s[ra * HID_STR + c0] = f2h2(hx, hy);
                *(uint32_t*)&in_s[rb * HID_STR + c0] = f2h2(hz, hw);
            }
        }
        __syncthreads();

        // ---- GEMM C: xf = h @ wC[layer+1] ----
        #pragma unroll
        for (int mi = 0; mi < 3; mi++)
            #pragma unroll
            for (int ni = 0; ni < 4; ni++)
                acc[mi][ni] = make_float4(0.f, 0.f, 0.f, 0.f);
        #pragma unroll
        for (int kt = 0; kt < 8; kt++) {
            uint32_t a0[4], a1[4], a2[4];
            ldsm4(a0, &in_s[(mbase + lrow) * HID_STR + kt * 16 + lcol]);
            ldsm4(a1, &in_s[(mbase + 16 + lrow) * HID_STR + kt * 16 + lcol]);
            ldsm4(a2, &in_s[(mbase + 32 + lrow) * HID_STR + kt * 16 + lcol]);
            #pragma unroll
            for (int ni = 0; ni < 4; ni++) {
                uint2 b = wCf[((nb + ni) * 8 + kt) * 32 + lid];
                mma16816(acc[0][ni], a0, b);
                mma16816(acc[1][ni], a1, b);
                mma16816(acc[2][ni], a2, b);
            }
        }
        #pragma unroll
        for (int mi = 0; mi < 3; mi++) {
            int ra = mbase + mi * 16 + gid;
            int rb = ra + 8;
            int na = n0 + ra, nbn = n0 + rb;
            #pragma unroll
            for (int ni = 0; ni < 4; ni++) {
                int c0 = (nb + ni) * 8 + 2 * tg;
                float4 v = acc[mi][ni];
                if (na < N_NODES)
                    *(float2*)&g_xf[(size_t)na * 128 + c0] = make_float2(v.x, v.y);
                if (nbn < N_NODES)
                    *(float2*)&g_xf[(size_t)nbn * 128 + c0] = make_float2(v.z, v.w);
            }
        }
        __syncthreads();
    }
}

// ---------------- node kernel, last layer: M=128 + output head --------------
__global__ __launch_bounds__(512, 1) void node_last_kernel(
        const float* __restrict__ bA, const float* __restrict__ bB,
        const float* __restrict__ bO1, const float* __restrict__ bO2,
        const int* __restrict__ batch) {
    extern __shared__ char smraw[];
    __half* in_s = (__half*)smraw;                     // 34816
    __half* x_s  = (__half*)(smraw + 34816);           // 34816
    uint2*  wAf  = (uint2*)(smraw + 69632);
    uint2*  wBf  = (uint2*)(smraw + 102400);
    uint2*  wCf  = (uint2*)(smraw + 135168);           // out1
    uint2*  wDf  = (uint2*)(smraw + 167936);           // out2
    float*  bA_s = (float*)(smraw + 200704);
    float*  bB_s = bA_s + 128;
    float*  bO1_s = bB_s + 128;
    float*  bO2_s = bO1_s + 128;
    int*    batch_s = (int*)(bO2_s + 128);

    int tid = threadIdx.x;
    int wid = tid >> 5;
    int lid = tid & 31;
    int gid = lid >> 2;
    int tg  = lid & 3;
    int lrow = lid & 15;
    int lcol = (lid >> 4) << 3;

    int mbase = (wid & 3) * 32;
    int nb    = (wid >> 2) * 4;

    if (tid < 128) {
        bA_s[tid] = bA[tid]; bB_s[tid] = bB[tid];
        bO1_s[tid] = bO1[tid]; bO2_s[tid] = bO2[tid];
    }
    for (int i = tid; i < 2048; i += 512) {
        ((uint4*)wAf)[i] = ((const uint4*)g_wAf[NLAYERS - 1])[i];
        ((uint4*)wBf)[i] = ((const uint4*)g_wBf[NLAYERS - 1])[i];
        ((uint4*)wCf)[i] = ((const uint4*)g_wO1f)[i];
        ((uint4*)wDf)[i] = ((const uint4*)g_wO2f)[i];
    }
    __syncthreads();

    for (int tile = blockIdx.x; tile < NODE_TILES; tile += gridDim.x) {
        int n0 = tile * 128;
        for (int i = tid; i < 128 * 32; i += 512) {
            int r = i >> 5, c4 = i & 31;
            float4 v = make_float4(0.f, 0.f, 0.f, 0.f);
            if (n0 + r < N_NODES)
                v = ((const float4*)&g_agg[(size_t)(n0 + r) * 128])[c4];
            *(uint2*)&in_s[r * HID_STR + c4 * 4] = make_uint2(f2h2(v.x, v.y), f2h2(v.z, v.w));
        }
        if (tid < 128)
            batch_s[tid] = (n0 + tid < N_NODES) ? batch[n0 + tid] : 0;
        __syncthreads();

        float4 acc[2][4];
        // ---- GEMM A ----
        #pragma unroll
        for (int mi = 0; mi < 2; mi++)
            #pragma unroll
            for (int ni = 0; ni < 4; ni++)
                acc[mi][ni] = make_float4(0.f, 0.f, 0.f, 0.f);
        #pragma unroll
        for (int kt = 0; kt < 8; kt++) {
            uint32_t a0[4], a1[4];
            ldsm4(a0, &in_s[(mbase + lrow) * HID_STR + kt * 16 + lcol]);
            ldsm4(a1, &in_s[(mbase + 16 + lrow) * HID_STR + kt * 16 + lcol]);
            #pragma unroll
            for (int ni = 0; ni < 4; ni++) {
                uint2 b = wAf[((nb + ni) * 8 + kt) * 32 + lid];
                mma16816(acc[0][ni], a0, b);
                mma16816(acc[1][ni], a1, b);
            }
        }
        #pragma unroll
        for (int mi = 0; mi < 2; mi++) {
            int ra = mbase + mi * 16 + gid;
            int rb = ra + 8;
            #pragma unroll
            for (int ni = 0; ni < 4; ni++) {
                int c0 = (nb + ni) * 8 + 2 * tg;
                float4 v = acc[mi][ni];
                float ba = bA_s[c0], bb = bA_s[c0 + 1];
                *(uint32_t*)&x_s[ra * HID_STR + c0] =
                    f2h2(sspf_fast(v.x + ba), sspf_fast(v.y + bb));
                *(uint32_t*)&x_s[rb * HID_STR + c0] =
                    f2h2(sspf_fast(v.z + ba), sspf_fast(v.w + bb));
            }
        }
        __syncthreads();

        // ---- GEMM B: h += x @ wB + bB ----
        #pragma unroll
        for (int mi = 0; mi < 2; mi++)
            #pragma unroll
            for (int ni = 0; ni < 4; ni++)
                acc[mi][ni] = make_float4(0.f, 0.f, 0.f, 0.f);
        #pragma unroll
        for (int kt = 0; kt < 8; kt++) {
            uint32_t a0[4], a1[4];
            ldsm4(a0, &x_s[(mbase + lrow) * HID_STR + kt * 16 + lcol]);
            ldsm4(a1, &x_s[(mbase + 16 + lrow) * HID_STR + kt * 16 + lcol]);
            #pragma unroll
            for (int ni = 0; ni < 4; ni++) {
                uint2 b = wBf[((nb + ni) * 8 + kt) * 32 + lid];
                mma16816(acc[0][ni], a0, b);
                mma16816(acc[1][ni], a1, b);
            }
        }
        #pragma unroll
        for (int mi = 0; mi < 2; mi++) {
            int ra = mbase + mi * 16 + gid;
            int rb = ra + 8;
            int na = n0 + ra, nbn = n0 + rb;
            #pragma unroll
            for (int ni = 0; ni < 4; ni++) {
                int c0 = (nb + ni) * 8 + 2 * tg;
                float4 v = acc[mi][ni];
                float ba = bB_s[c0], bb = bB_s[c0 + 1];
                float hx = 0.f, hy = 0.f, hz = 0.f, hw = 0.f;
                if (na < N_NODES) {
                    float2 hv = *(float2*)&g_h[(size_t)na * 128 + c0];
                    hx = hv.x + v.x + ba;
                    hy = hv.y + v.y + bb;
                }
                if (nbn < N_NODES) {
                    float2 hv = *(float2*)&g_h[(size_t)nbn * 128 + c0];
                    hz = hv.x + v.z + ba;
                    hw = hv.y + v.w + bb;
                }
                *(uint32_t*)&in_s[ra * HID_STR + c0] = f2h2(hx, hy);
                *(uint32_t*)&in_s[rb * HID_STR + c0] = f2h2(hz, hw);
            }
        }
        __syncthreads();

        // ---- output head: x = ssp(h @ out1 + bO1) ----
        #pragma unroll
        for (int mi = 0; mi < 2; mi++)
            #pragma unroll
            for (int ni = 0; ni < 4; ni++)
                acc[mi][ni] = make_float4(0.f, 0.f, 0.f, 0.f);
        #pragma unroll
        for (int kt = 0; kt < 8; kt++) {
            uint32_t a0[4], a1[4];
            ldsm4(a0, &in_s[(mbase + lrow) * HID_STR + kt * 16 + lcol]);
            ldsm4(a1, &in_s[(mbase + 16 + lrow) * HID_STR + kt * 16 + lcol]);
            #pragma unroll
            for (int ni = 0; ni < 4; ni++) {
                uint2 b = wCf[((nb + ni) * 8 + kt) * 32 + lid];
                mma16816(acc[0][ni], a0, b);
                mma16816(acc[1][ni], a1, b);
            }
        }
        #pragma unroll
        for (int mi = 0; mi < 2; mi++) {
            int ra = mbase + mi * 16 + gid;
            int rb = ra + 8;
            #pragma unroll
            for (int ni = 0; ni < 4; ni++) {
                int c0 = (nb + ni) * 8 + 2 * tg;
                float4 v = acc[mi][ni];
                float ba = bO1_s[c0], bb = bO1_s[c0 + 1];
                *(uint32_t*)&x_s[ra * HID_STR + c0] =
                    f2h2(sspf_fast(v.x + ba), sspf_fast(v.y + bb));
                *(uint32_t*)&x_s[rb * HID_STR + c0] =
                    f2h2(sspf_fast(v.z + ba), sspf_fast(v.w + bb));
            }
        }
        __syncthreads();

        // ---- output head: out = x @ out2 + bO2 -> g_sums[batch] ----
        #pragma unroll
        for (int mi = 0; mi < 2; mi++)
            #pragma unroll
            for (int ni = 0; ni < 4; ni++)
                acc[mi][ni] = make_float4(0.f, 0.f, 0.f, 0.f);
        #pragma unroll
        for (int kt = 0; kt < 8; kt++) {
            uint32_t a0[4], a1[4];
            ldsm4(a0, &x_s[(mbase + lrow) * HID_STR + kt * 16 + lcol]);
            ldsm4(a1, &x_s[(mbase + 16 + lrow) * HID_STR + kt * 16 + lcol]);
            #pragma unroll
            for (int ni = 0; ni < 4; ni++) {
                uint2 b = wDf[((nb + ni) * 8 + kt) * 32 + lid];
                mma16816(acc[0][ni], a0, b);
                mma16816(acc[1][ni], a1, b);
            }
        }
        #pragma unroll
        for (int mi = 0; mi < 2; mi++) {
            int ra = mbase + mi * 16 + gid;
            int rb = ra + 8;
            int na = n0 + ra, nbn = n0 + rb;
            #pragma unroll
            for (int ni = 0; ni < 4; ni++) {
                int c0 = (nb + ni) * 8 + 2 * tg;
                float4 v = acc[mi][ni];
                float2 bv = *(const float2*)&bO2_s[c0];
                if (na < N_NODES) {
                    float2 o = make_float2(v.x + bv.x, v.y + bv.y);
                    atomicAdd((float2*)&g_sums[batch_s[ra] * 128 + c0], o);
                }
                if (nbn < N_NODES) {
                    float2 o = make_float2(v.z + bv.x, v.w + bv.y);
                    atomicAdd((float2*)&g_sums[batch_s[rb] * 128 + c0], o);
                }
            }
        }
        __syncthreads();
    }
}

__global__ void finalize_kernel(float* __restrict__ out) {
    int i = blockIdx.x * blockDim.x + threadIdx.x;
    if (i >= NGRAPH * HDIM) return;
    out[i] = g_sums[i] / fmaxf(g_cnt[i >> 7], 1.0f);
}

// ---------------- launcher ----------------
extern "C" void kernel_launch(void* const* d_in, const int* in_sizes, int n_in,
                              void* d_out, int out_size) {
    const int*   z       = (const int*)d_in[0];
    const float* pos     = (const float*)d_in[1];
    const int*   ei      = (const int*)d_in[2];
    const int*   batch   = (const int*)d_in[3];
    const float* emb     = (const float*)d_in[4];
    const float* mlp_w1  = (const float*)d_in[5];
    const float* mlp_b1  = (const float*)d_in[6];
    const float* mlp_w2  = (const float*)d_in[7];
    const float* mlp_b2  = (const float*)d_in[8];
    const float* conv_w1 = (const float*)d_in[9];
    const float* conv_w2 = (const float*)d_in[10];
    const float* conv_b2 = (const float*)d_in[11];
    const float* lin_w   = (const float*)d_in[12];
    const float* lin_b   = (const float*)d_in[13];
    const float* out1_w  = (const float*)d_in[14];
    const float* out1_b  = (const float*)d_in[15];
    const float* out2_w  = (const float*)d_in[16];
    const float* out2_b  = (const float*)d_in[17];
    float* out = (float*)d_out;

    const int* src = ei;
    const int* dst = ei + N_EDGES;

    const int EDGE_SMEM = 104960;
    const int MID_SMEM  = 203776;
    const int LAST_SMEM = 203264;
    const int XF0_SMEM  = 67584;

    cudaFuncSetAttribute(edge_mma_kernel, cudaFuncAttributeMaxDynamicSharedMemorySize, EDGE_SMEM);
    cudaFuncSetAttribute(node_mid_kernel, cudaFuncAttributeMaxDynamicSharedMemorySize, MID_SMEM);
    cudaFuncSetAttribute(node_last_kernel, cudaFuncAttributeMaxDynamicSharedMemorySize, LAST_SMEM);
    cudaFuncSetAttribute(xf0_kernel, cudaFuncAttributeMaxDynamicSharedMemorySize, XF0_SMEM);

    zero_all_kernel<<<(N_NODES * HDIM + 255) / 256, 256>>>();
    init_h_kernel<<<(N_NODES * HDIM + 255) / 256, 256>>>(z, emb, batch);
    dist_hist_kernel<<<(N_EDGES + 255) / 256, 256>>>(src, dst, pos);
    scan1_kernel<<<SCAN_BLOCKS, 1024>>>();
    scan2_kernel<<<1, 32>>>();
    scan3_kernel<<<SCAN_BLOCKS, 1024>>>();
    scatter_kernel<<<(N_EDGES + 255) / 256, 256>>>(src, dst);
    build_frags_kernel<<<(NLAYERS * 4096 + 255) / 256, 256>>>(
        mlp_w1, mlp_w2, conv_w2, lin_w, conv_w1, out1_w, out2_w);

    xf0_kernel<<<NODE_TILES, 256, XF0_SMEM>>>();   // xf for layer 0

    for (int l = 0; l < NLAYERS - 1; l++) {
        edge_mma_kernel<<<296, 256, EDGE_SMEM>>>(
            l, mlp_b1 + (size_t)l * 128, mlp_b2 + (size_t)l * 128);
        node_mid_kernel<<<MID_TILES, 512, MID_SMEM>>>(
            l, conv_b2 + (size_t)l * 128, lin_b + (size_t)l * 128);
    }
    {
        int l = NLAYERS - 1;
        edge_mma_kernel<<<296, 256, EDGE_SMEM>>>(
            l, mlp_b1 + (size_t)l * 128, mlp_b2 + (size_t)l * 128);
        node_last_kernel<<<148, 512, LAST_SMEM>>>(
            conv_b2 + (size_t)l * 128, lin_b + (size_t)l * 128,
            out1_b, out2_b, batch);
    }

    finalize_kernel<<<(NGRAPH * HDIM + 255) / 256, 256>>>(out);
}